// round 3
// baseline (speedup 1.0000x reference)
#include <cuda_runtime.h>
#include <cstdint>

#define BATCH 8
#define NPTS 2048
#define KNN 20
#define M_EDGES (BATCH * NPTS * KNN)   // 327680
#define LDC 512
#define FIN_O 1024

// ---------------- scratch (device globals; no allocations allowed) -------------
__device__ float  g_e    [(size_t)M_EDGES * 256];            // edge features, worst 2C=256 (335MB)
__device__ float  g_hpre [(size_t)M_EDGES * 256];            // pre-BN conv output (335MB)
__device__ float  g_dist [(size_t)BATCH * NPTS * NPTS];      // pairwise sq distances (134MB)
__device__ int    g_idx  [M_EDGES];                          // knn indices
__device__ float  g_xcat [(size_t)BATCH * NPTS * LDC];       // concatenated layer outputs
__device__ float  g_fin  [(size_t)BATCH * NPTS * FIN_O];     // final conv output pre-maxpool
__device__ double g_sum  [256];
__device__ double g_sumsq[256];
__device__ float  g_scale[256];
__device__ float  g_shift[256];

__device__ __forceinline__ float neg_inf() { return __int_as_float(0xff800000); }
__device__ __forceinline__ float pos_inf() { return __int_as_float(0x7f800000); }

// ---------------- pairwise squared distances, tiled --------------------------
// D[b,n,m] = ||h[b,n]-h[b,m]||^2
__global__ void dist_kernel(const float* __restrict__ h, int ld, int C) {
    __shared__ float As[16][17];
    __shared__ float Bs[16][17];
    int b   = blockIdx.z;
    int row = blockIdx.y * 16 + threadIdx.y;
    int col = blockIdx.x * 16 + threadIdx.x;
    const float* hb = h + (size_t)b * NPTS * ld;
    float acc = 0.f;
    for (int c0 = 0; c0 < C; c0 += 16) {
        int ca = c0 + threadIdx.x;
        As[threadIdx.y][threadIdx.x] =
            (ca < C) ? hb[(size_t)(blockIdx.y * 16 + threadIdx.y) * ld + ca] : 0.f;
        Bs[threadIdx.y][threadIdx.x] =
            (ca < C) ? hb[(size_t)(blockIdx.x * 16 + threadIdx.y) * ld + ca] : 0.f;
        __syncthreads();
#pragma unroll
        for (int k = 0; k < 16; k++) {
            float d = As[threadIdx.y][k] - Bs[threadIdx.x][k];
            acc = fmaf(d, d, acc);
        }
        __syncthreads();
    }
    g_dist[((size_t)b * NPTS + row) * NPTS + col] = acc;
}

// ---------------- warp-per-row top-K (smallest distances) ---------------------
__global__ void topk_kernel() {
    int gwarp = (blockIdx.x * blockDim.x + threadIdx.x) >> 5;
    int lane  = threadIdx.x & 31;
    if (gwarp >= BATCH * NPTS) return;
    const float* drow = &g_dist[(size_t)gwarp * NPTS];

    float best[KNN];
    int   bidx[KNN];
#pragma unroll
    for (int i = 0; i < KNN; i++) { best[i] = pos_inf(); bidx[i] = -1; }

    for (int m = lane; m < NPTS; m += 32) {
        float d = drow[m];
        if (d < best[KNN - 1]) {
            int p = KNN - 1;
            while (p > 0 && best[p - 1] > d) {
                best[p] = best[p - 1]; bidx[p] = bidx[p - 1]; p--;
            }
            best[p] = d; bidx[p] = m;
        }
    }
    // merge 32 sorted lists: 20 rounds of warp argmin
    int ptr = 0;
    for (int s = 0; s < KNN; s++) {
        float v  = (ptr < KNN) ? best[ptr] : pos_inf();
        int   ci = (ptr < KNN) ? bidx[ptr] : -1;
        float mv = v; int ml = lane;
#pragma unroll
        for (int off = 16; off > 0; off >>= 1) {
            float ov = __shfl_down_sync(0xffffffffu, mv, off);
            int   ol = __shfl_down_sync(0xffffffffu, ml, off);
            if (ov < mv) { mv = ov; ml = ol; }
        }
        ml = __shfl_sync(0xffffffffu, ml, 0);
        int widx = __shfl_sync(0xffffffffu, ci, ml);
        if (lane == ml) ptr++;
        if (lane == 0) g_idx[gwarp * KNN + s] = widx;
    }
}

// ---------------- edge feature build: e = [nbr - ctr, ctr] --------------------
__global__ void edge_kernel(const float* __restrict__ h, int ld, int C) {
    int t = blockIdx.x * blockDim.x + threadIdx.x;
    if (t >= M_EDGES * C) return;
    int c  = t % C;
    int m  = t / C;              // edge index (b*N+n)*KNN + k
    int bn = m / KNN;            // b*N+n
    int b  = bn / NPTS;
    int nbr = g_idx[m];
    float ctr = h[(size_t)bn * ld + c];
    float nb  = h[(size_t)(b * NPTS + nbr) * ld + c];
    g_e[(size_t)m * (2 * C) + c]     = nb - ctr;
    g_e[(size_t)m * (2 * C) + C + c] = ctr;
}

// ---------------- zero BN accumulators ----------------------------------------
__global__ void zero_stats() {
    int t = threadIdx.x;
    if (t < 256) { g_sum[t] = 0.0; g_sumsq[t] = 0.0; }
}

// ---------------- SGEMM: C[M,N] = A[M,K] * W[N,K]^T + bias; optional stats ----
__global__ void gemm_kernel(const float* __restrict__ A, const float* __restrict__ W,
                            const float* __restrict__ bias, float* __restrict__ Cout,
                            int Mrows, int Kdim, int Ncols, int doStats) {
    __shared__ float  As[64][8];
    __shared__ float  Bs[8][65];
    __shared__ double sSum[64];
    __shared__ double sSq[64];
    int tid = threadIdx.x;          // 256
    int tx  = tid & 15, ty = tid >> 4;
    int m0  = blockIdx.x * 64;
    int n0  = blockIdx.y * 64;

    if (doStats && tid < 64) { sSum[tid] = 0.0; sSq[tid] = 0.0; }

    float acc[4][4];
#pragma unroll
    for (int i = 0; i < 4; i++)
#pragma unroll
        for (int j = 0; j < 4; j++) acc[i][j] = 0.f;

    for (int k0 = 0; k0 < Kdim; k0 += 8) {
#pragma unroll
        for (int j = 0; j < 2; j++) {
            int l = tid * 2 + j;
            int ar = l >> 3, ac = l & 7;
            int kk = k0 + ac;
            As[ar][ac] = (kk < Kdim) ? A[(size_t)(m0 + ar) * Kdim + kk] : 0.f;
        }
#pragma unroll
        for (int j = 0; j < 2; j++) {
            int l = tid * 2 + j;
            int n = l >> 3, kk = l & 7;
            int k = k0 + kk;
            Bs[kk][n] = (k < Kdim) ? W[(size_t)(n0 + n) * Kdim + k] : 0.f;
        }
        __syncthreads();
#pragma unroll
        for (int k = 0; k < 8; k++) {
            float ra[4], rb[4];
#pragma unroll
            for (int i = 0; i < 4; i++) ra[i] = As[ty * 4 + i][k];
#pragma unroll
            for (int j = 0; j < 4; j++) rb[j] = Bs[k][tx * 4 + j];
#pragma unroll
            for (int i = 0; i < 4; i++)
#pragma unroll
                for (int j = 0; j < 4; j++) acc[i][j] = fmaf(ra[i], rb[j], acc[i][j]);
        }
        __syncthreads();
    }

#pragma unroll
    for (int j = 0; j < 4; j++) {
        int o = n0 + tx * 4 + j;
        float bv = bias[o];
        double ps = 0.0, pq = 0.0;
#pragma unroll
        for (int i = 0; i < 4; i++) {
            float v = acc[i][j] + bv;
            Cout[(size_t)(m0 + ty * 4 + i) * Ncols + o] = v;
            ps += (double)v;
            pq += (double)v * (double)v;
        }
        if (doStats) {
            atomicAdd(&sSum[tx * 4 + j], ps);
            atomicAdd(&sSq[tx * 4 + j], pq);
        }
    }
    if (doStats) {
        __syncthreads();
        if (tid < 64) {
            atomicAdd(&g_sum[n0 + tid],   sSum[tid]);
            atomicAdd(&g_sumsq[n0 + tid], sSq[tid]);
        }
    }
}

// ---------------- BN scale/shift from sums ------------------------------------
__global__ void finalize_stats(const float* __restrict__ gam,
                               const float* __restrict__ bet, int O, double cnt) {
    int o = blockIdx.x * blockDim.x + threadIdx.x;
    if (o >= O) return;
    double mean = g_sum[o] / cnt;
    double var  = g_sumsq[o] / cnt - mean * mean;
    float inv = rsqrtf((float)var + 1e-5f);
    float sc  = gam[o] * inv;
    g_scale[o] = sc;
    g_shift[o] = bet[o] - (float)mean * sc;
}

// ---------------- BN + LeakyReLU + max over k ---------------------------------
__global__ void bn_relu_max(int O, int outOff) {
    int t = blockIdx.x * blockDim.x + threadIdx.x;
    if (t >= BATCH * NPTS * O) return;
    int o  = t % O;
    int bn = t / O;
    float sc = g_scale[o], sh = g_shift[o];
    float mx = neg_inf();
    size_t base = (size_t)bn * KNN * O + o;
#pragma unroll 5
    for (int k = 0; k < KNN; k++) {
        float v = g_hpre[base + (size_t)k * O];
        v = fmaf(v, sc, sh);
        v = (v >= 0.f) ? v : 0.2f * v;
        mx = fmaxf(mx, v);
    }
    g_xcat[(size_t)bn * LDC + outOff + o] = mx;
}

// ---------------- global max pool over N --------------------------------------
__global__ void max_over_n(float* __restrict__ out) {
    int t = blockIdx.x * blockDim.x + threadIdx.x;
    if (t >= BATCH * FIN_O) return;
    int o = t % FIN_O, b = t / FIN_O;
    const float* base = g_fin + (size_t)b * NPTS * FIN_O + o;
    float mx = neg_inf();
#pragma unroll 4
    for (int n = 0; n < NPTS; n++) mx = fmaxf(mx, base[(size_t)n * FIN_O]);
    out[t] = mx;
}

// ==============================================================================
extern "C" void kernel_launch(void* const* d_in, const int* in_sizes, int n_in,
                              void* d_out, int out_size) {
    const float* x  = (const float*)d_in[0];
    const float* Wm[4], *bm[4], *gm[4], *bem[4];
    for (int i = 0; i < 4; i++) {
        Wm[i]  = (const float*)d_in[1 + 4 * i];
        bm[i]  = (const float*)d_in[2 + 4 * i];
        gm[i]  = (const float*)d_in[3 + 4 * i];
        bem[i] = (const float*)d_in[4 + 4 * i];
    }
    const float* Wf = (const float*)d_in[17];
    const float* bf = (const float*)d_in[18];
    float* out = (float*)d_out;

    float *e_ptr, *hpre_ptr, *xcat_ptr, *fin_ptr;
    cudaGetSymbolAddress((void**)&e_ptr,    g_e);
    cudaGetSymbolAddress((void**)&hpre_ptr, g_hpre);
    cudaGetSymbolAddress((void**)&xcat_ptr, g_xcat);
    cudaGetSymbolAddress((void**)&fin_ptr,  g_fin);

    const int Hs[4]   = {64, 64, 128, 256};
    const int offs[4] = {0, 64, 128, 256};      // output channel offsets in xcat

    const float* hsrc = x;
    int ld = 3;
    int C  = 3;

    for (int i = 0; i < 4; i++) {
        int O = Hs[i];
        int Kdim = 2 * C;

        dist_kernel<<<dim3(NPTS / 16, NPTS / 16, BATCH), dim3(16, 16)>>>(hsrc, ld, C);
        topk_kernel<<<(BATCH * NPTS * 32 + 255) / 256, 256>>>();
        edge_kernel<<<((size_t)M_EDGES * C + 255) / 256, 256>>>(hsrc, ld, C);
        zero_stats<<<1, 256>>>();
        gemm_kernel<<<dim3(M_EDGES / 64, O / 64), 256>>>(
            e_ptr, Wm[i], bm[i], hpre_ptr, M_EDGES, Kdim, O, 1);
        finalize_stats<<<1, 256>>>(gm[i], bem[i], O, (double)M_EDGES);
        bn_relu_max<<<((size_t)BATCH * NPTS * O + 255) / 256, 256>>>(O, offs[i]);

        hsrc = xcat_ptr + offs[i];
        ld = LDC;
        C  = O;
    }

    // final 1x1 conv (GEMM) + global max pool over N
    gemm_kernel<<<dim3(BATCH * NPTS / 64, FIN_O / 64), 256>>>(
        xcat_ptr, Wf, bf, fin_ptr, BATCH * NPTS, LDC, FIN_O, 0);
    max_over_n<<<(BATCH * FIN_O + 255) / 256, 256>>>(out);
}

// round 12
// speedup vs baseline: 1.2420x; 1.2420x over previous
#include <cuda_runtime.h>
#include <cstdint>

#define BATCH 8
#define NPTS 2048
#define BN_TOT (BATCH * NPTS)          // 16384
#define KNN 20
#define M_EDGES (BN_TOT * KNN)         // 327680
#define LDCAT 512
#define FIN_O 1024

// ---------------- scratch (device globals; no allocations allowed) -------------
__device__ float  g_dist[(size_t)BATCH * NPTS * NPTS];   // 134MB
__device__ int    g_idx [M_EDGES];
__device__ float  g_e   [(size_t)M_EDGES * 256];         // edge feats, max 2C=256 (335MB)
__device__ float  g_hpre[(size_t)M_EDGES * 256];         // pre-BN conv out, max O=256
__device__ float  g_xcat[(size_t)BN_TOT * LDCAT];
__device__ float  g_fin [(size_t)BN_TOT * FIN_O];
__device__ double g_sum  [256];
__device__ double g_sumsq[256];
__device__ float  g_scale[256];
__device__ float  g_shift[256];

__device__ __forceinline__ float neg_inf() { return __int_as_float(0xff800000); }
__device__ __forceinline__ float pos_inf() { return __int_as_float(0x7f800000); }

// ---------------- pairwise sq distances: 128x128 tile, 8x8 micro, DIFF FORM ----
// Sequential fmaf over c => bitwise-identical to the R3 passing kernel.
__global__ __launch_bounds__(256, 2)
void dist_gemm(const float* __restrict__ h, int ld, int C) {
    __shared__ float As[8][132];
    __shared__ float Bs[8][132];
    int b   = blockIdx.z;
    const float* hb = h + (size_t)b * NPTS * ld;
    int tid = threadIdx.x;
    int tx = tid & 15, ty = tid >> 4;
    int m0 = blockIdx.y * 128, n0 = blockIdx.x * 128;
    int r  = tid >> 1, c4 = (tid & 1) * 4;

    float acc[8][8];
#pragma unroll
    for (int i = 0; i < 8; i++)
#pragma unroll
        for (int j = 0; j < 8; j++) acc[i][j] = 0.f;

    const float* Arow = hb + (size_t)(m0 + r) * ld;
    const float* Brow = hb + (size_t)(n0 + r) * ld;

    for (int k0 = 0; k0 < C; k0 += 8) {
#pragma unroll
        for (int j = 0; j < 4; j++) {
            int k = k0 + c4 + j;
            As[c4 + j][r] = (k < C) ? Arow[k] : 0.f;
            Bs[c4 + j][r] = (k < C) ? Brow[k] : 0.f;
        }
        __syncthreads();
#pragma unroll
        for (int k = 0; k < 8; k++) {
            float a[8], bb[8];
            *(float4*)(a)      = *(const float4*)&As[k][ty * 8];
            *(float4*)(a + 4)  = *(const float4*)&As[k][ty * 8 + 4];
            *(float4*)(bb)     = *(const float4*)&Bs[k][tx * 8];
            *(float4*)(bb + 4) = *(const float4*)&Bs[k][tx * 8 + 4];
#pragma unroll
            for (int i = 0; i < 8; i++)
#pragma unroll
                for (int j = 0; j < 8; j++) {
                    float d = a[i] - bb[j];
                    acc[i][j] = fmaf(d, d, acc[i][j]);
                }
        }
        __syncthreads();
    }

    float* dbase = g_dist + (size_t)b * NPTS * NPTS;
#pragma unroll
    for (int i = 0; i < 8; i++) {
        float* drow = dbase + (size_t)(m0 + ty * 8 + i) * NPTS;
#pragma unroll
        for (int jj = 0; jj < 2; jj++) {
            float4 v;
            v.x = acc[i][jj * 4 + 0];
            v.y = acc[i][jj * 4 + 1];
            v.z = acc[i][jj * 4 + 2];
            v.w = acc[i][jj * 4 + 3];
            *(float4*)&drow[n0 + tx * 8 + jj * 4] = v;
        }
    }
}

// ---------------- warp-per-row top-K (smallest distances) ---------------------
__global__ void topk_kernel() {
    int gwarp = (blockIdx.x * blockDim.x + threadIdx.x) >> 5;
    int lane  = threadIdx.x & 31;
    if (gwarp >= BN_TOT) return;
    const float* drow = &g_dist[(size_t)gwarp * NPTS];

    float best[KNN];
    int   bidx[KNN];
#pragma unroll
    for (int i = 0; i < KNN; i++) { best[i] = pos_inf(); bidx[i] = -1; }

    for (int m = lane; m < NPTS; m += 32) {
        float d = drow[m];
        if (d < best[KNN - 1]) {
            int p = KNN - 1;
            while (p > 0 && best[p - 1] > d) {
                best[p] = best[p - 1]; bidx[p] = bidx[p - 1]; p--;
            }
            best[p] = d; bidx[p] = m;
        }
    }
    int ptr = 0;
    for (int s = 0; s < KNN; s++) {
        float v  = (ptr < KNN) ? best[ptr] : pos_inf();
        int   ci = (ptr < KNN) ? bidx[ptr] : -1;
        float mv = v; int ml = lane;
#pragma unroll
        for (int off = 16; off > 0; off >>= 1) {
            float ov = __shfl_down_sync(0xffffffffu, mv, off);
            int   ol = __shfl_down_sync(0xffffffffu, ml, off);
            if (ov < mv) { mv = ov; ml = ol; }
        }
        ml = __shfl_sync(0xffffffffu, ml, 0);
        int widx = __shfl_sync(0xffffffffu, ci, ml);
        if (lane == ml) ptr++;
        if (lane == 0) g_idx[gwarp * KNN + s] = widx;
    }
}

// ---------------- edge feature build: e = [nbr - ctr, ctr] --------------------
__global__ void edge_kernel(const float* __restrict__ h, int ld, int C) {
    int t = blockIdx.x * blockDim.x + threadIdx.x;
    if (t >= M_EDGES * C) return;
    int c  = t % C;
    int m  = t / C;              // edge index (b*N+n)*KNN + k
    int bn = m / KNN;
    int b  = bn / NPTS;
    int nbr = g_idx[m];
    float ctr = h[(size_t)bn * ld + c];
    float nb  = h[(size_t)(b * NPTS + nbr) * ld + c];
    g_e[(size_t)m * (2 * C) + c]     = nb - ctr;
    g_e[(size_t)m * (2 * C) + C + c] = ctr;
}

// ---------------- BN accumulators ----------------------------------------------
__global__ void zero_stats() {
    int t = threadIdx.x;
    if (t < 256) { g_sum[t] = 0.0; g_sumsq[t] = 0.0; }
}

// ---------------- tiled SGEMM: C[M,tileN] = A[M,K]*W[N,K]^T + bias (+stats) ----
// TN = columns per thread (8 -> 128-wide tile, 4 -> 64-wide tile).
// Per-output dot is accumulated sequentially over k => bitwise == R3 kernel.
template<int TN>
__global__ __launch_bounds__(256, 2)
void gemm_tile(const float* __restrict__ A, int lda,
               const float* __restrict__ W, int ldw,
               const float* __restrict__ bias,
               float* __restrict__ Cmat, int ldc,
               int Kd, int Nc, int doStats) {
    const int TILE_N = TN * 16;
    __shared__ float  As[8][132];
    __shared__ float  Bs[8][TILE_N + 4];
    __shared__ double sSum[TILE_N];
    __shared__ double sSq [TILE_N];

    int tid = threadIdx.x;
    int tx = tid & 15, ty = tid >> 4;
    int m0 = blockIdx.x * 128, n0 = blockIdx.y * TILE_N;
    int r  = tid >> 1, c4 = (tid & 1) * 4;

    if (doStats && tid < TILE_N) { sSum[tid] = 0.0; sSq[tid] = 0.0; }

    float acc[8][TN];
#pragma unroll
    for (int i = 0; i < 8; i++)
#pragma unroll
        for (int j = 0; j < TN; j++) acc[i][j] = 0.f;

    const float* Arow = A + (size_t)(m0 + r) * lda;
    const float* Wrow = (tid < TILE_N * 2) ? (W + (size_t)(n0 + (tid >> 1)) * ldw) : W;
    int wk4 = (tid & 1) * 4;

    for (int k0 = 0; k0 < Kd; k0 += 8) {
#pragma unroll
        for (int j = 0; j < 4; j++) {
            int k = k0 + c4 + j;
            As[c4 + j][r] = (k < Kd) ? Arow[k] : 0.f;
        }
        if (tid < TILE_N * 2) {
            int n = tid >> 1;
#pragma unroll
            for (int j = 0; j < 4; j++) {
                int k = k0 + wk4 + j;
                Bs[wk4 + j][n] = (k < Kd && (n0 + n) < Nc) ? Wrow[k] : 0.f;
            }
        }
        __syncthreads();
#pragma unroll
        for (int k = 0; k < 8; k++) {
            float a[8], bb[TN];
            *(float4*)(a)     = *(const float4*)&As[k][ty * 8];
            *(float4*)(a + 4) = *(const float4*)&As[k][ty * 8 + 4];
            *(float4*)(bb)    = *(const float4*)&Bs[k][tx * TN];
            if (TN == 8) *(float4*)(bb + 4) = *(const float4*)&Bs[k][tx * TN + 4];
#pragma unroll
            for (int i = 0; i < 8; i++)
#pragma unroll
                for (int j = 0; j < TN; j++)
                    acc[i][j] = fmaf(a[i], bb[j], acc[i][j]);
        }
        __syncthreads();
    }

#pragma unroll
    for (int j = 0; j < TN; j++) {
        int col = tx * TN + j;
        int n   = n0 + col;
        float bv = (n < Nc) ? bias[n] : 0.f;
        double ps = 0.0, pq = 0.0;
#pragma unroll
        for (int i = 0; i < 8; i++) {
            float v = acc[i][j] + bv;
            acc[i][j] = v;
            ps += (double)v;
            pq += (double)v * (double)v;
        }
        if (doStats) {
            atomicAdd(&sSum[col], ps);
            atomicAdd(&sSq[col],  pq);
        }
    }
#pragma unroll
    for (int i = 0; i < 8; i++) {
        float* crow = Cmat + (size_t)(m0 + ty * 8 + i) * ldc;
        if (n0 + tx * TN + TN - 1 < Nc) {
            *(float4*)&crow[n0 + tx * TN] = *(float4*)&acc[i][0];
            if (TN == 8) *(float4*)&crow[n0 + tx * TN + 4] = *(float4*)&acc[i][4];
        }
    }
    if (doStats) {
        __syncthreads();
        if (tid < TILE_N && (n0 + tid) < Nc) {
            atomicAdd(&g_sum[n0 + tid],   sSum[tid]);
            atomicAdd(&g_sumsq[n0 + tid], sSq[tid]);
        }
    }
}

__global__ void finalize_stats(const float* __restrict__ gam,
                               const float* __restrict__ bet, int O, double cnt) {
    int o = blockIdx.x * blockDim.x + threadIdx.x;
    if (o >= O) return;
    double mean = g_sum[o] / cnt;
    double var  = g_sumsq[o] / cnt - mean * mean;
    float inv = rsqrtf((float)var + 1e-5f);
    float sc  = gam[o] * inv;
    g_scale[o] = sc;
    g_shift[o] = bet[o] - (float)mean * sc;
}

// ---------------- BN + LeakyReLU + max over k ---------------------------------
__global__ void bn_relu_max(int O, int outOff) {
    int t = blockIdx.x * blockDim.x + threadIdx.x;
    if (t >= BN_TOT * O) return;
    int o  = t % O;
    int bn = t / O;
    float sc = g_scale[o], sh = g_shift[o];
    float mx = neg_inf();
    size_t base = (size_t)bn * KNN * O + o;
#pragma unroll 5
    for (int k = 0; k < KNN; k++) {
        float v = g_hpre[base + (size_t)k * O];
        v = fmaf(v, sc, sh);
        v = (v >= 0.f) ? v : 0.2f * v;
        mx = fmaxf(mx, v);
    }
    g_xcat[(size_t)bn * LDCAT + outOff + o] = mx;
}

// ---------------- global max pool over N --------------------------------------
__global__ void max_over_n(float* __restrict__ out) {
    int t = blockIdx.x * blockDim.x + threadIdx.x;
    if (t >= BATCH * FIN_O) return;
    int o = t % FIN_O, b = t / FIN_O;
    const float* base = g_fin + (size_t)b * NPTS * FIN_O + o;
    float mx = neg_inf();
#pragma unroll 4
    for (int n = 0; n < NPTS; n++) mx = fmaxf(mx, base[(size_t)n * FIN_O]);
    out[t] = mx;
}

// ==============================================================================
extern "C" void kernel_launch(void* const* d_in, const int* in_sizes, int n_in,
                              void* d_out, int out_size) {
    const float* x = (const float*)d_in[0];
    const float* Wm[4], *bm[4], *gm[4], *bem[4];
    for (int i = 0; i < 4; i++) {
        Wm[i]  = (const float*)d_in[1 + 4 * i];
        bm[i]  = (const float*)d_in[2 + 4 * i];
        gm[i]  = (const float*)d_in[3 + 4 * i];
        bem[i] = (const float*)d_in[4 + 4 * i];
    }
    const float* Wf = (const float*)d_in[17];
    const float* bf = (const float*)d_in[18];
    float* out = (float*)d_out;

    float *e_ptr, *hpre_ptr, *xcat_ptr, *fin_ptr;
    cudaGetSymbolAddress((void**)&e_ptr,    g_e);
    cudaGetSymbolAddress((void**)&hpre_ptr, g_hpre);
    cudaGetSymbolAddress((void**)&xcat_ptr, g_xcat);
    cudaGetSymbolAddress((void**)&fin_ptr,  g_fin);

    const int Hs[4]   = {64, 64, 128, 256};
    const int offs[4] = {0, 64, 128, 256};

    const float* hsrc = x;
    int ld = 3, C = 3;

    for (int i = 0; i < 4; i++) {
        int O = Hs[i];
        int Kd = 2 * C;

        dist_gemm<<<dim3(NPTS / 128, NPTS / 128, BATCH), 256>>>(hsrc, ld, C);
        topk_kernel<<<BN_TOT / 8, 256>>>();
        edge_kernel<<<((size_t)M_EDGES * C + 255) / 256, 256>>>(hsrc, ld, C);
        zero_stats<<<1, 256>>>();

        if (O == 64) {
            gemm_tile<4><<<dim3(M_EDGES / 128, 1), 256>>>(
                e_ptr, Kd, Wm[i], Kd, bm[i], hpre_ptr, O, Kd, O, 1);
        } else {
            gemm_tile<8><<<dim3(M_EDGES / 128, O / 128), 256>>>(
                e_ptr, Kd, Wm[i], Kd, bm[i], hpre_ptr, O, Kd, O, 1);
        }

        finalize_stats<<<1, 256>>>(gm[i], bem[i], O, (double)M_EDGES);
        bn_relu_max<<<((size_t)BN_TOT * O + 255) / 256, 256>>>(O, offs[i]);

        hsrc = xcat_ptr + offs[i];
        ld = LDCAT;
        C  = O;
    }

    // final 1x1 conv (GEMM) + global max pool over N
    gemm_tile<8><<<dim3(BN_TOT / 128, FIN_O / 128), 256>>>(
        xcat_ptr, LDCAT, Wf, LDCAT, bf, fin_ptr, FIN_O, LDCAT, FIN_O, 0);
    max_over_n<<<(BATCH * FIN_O + 255) / 256, 256>>>(out);
}

// round 13
// speedup vs baseline: 1.3188x; 1.0618x over previous
#include <cuda_runtime.h>
#include <cstdint>

#define BATCH 8
#define NPTS 2048
#define BN_TOT (BATCH * NPTS)          // 16384
#define KNN 20
#define M_EDGES (BN_TOT * KNN)         // 327680
#define LDCAT 512
#define FIN_O 1024

// ---------------- scratch (device globals; no allocations allowed) -------------
__device__ float  g_dist[(size_t)BATCH * NPTS * NPTS];   // 134MB
__device__ int    g_idx [M_EDGES];
__device__ float  g_hpre[(size_t)M_EDGES * 256];         // pre-BN conv out, max O=256
__device__ float  g_xcat[(size_t)BN_TOT * LDCAT];
__device__ float  g_fin [(size_t)BN_TOT * FIN_O];
__device__ double g_sum  [256];
__device__ double g_sumsq[256];
__device__ float  g_scale[256];
__device__ float  g_shift[256];

__device__ __forceinline__ float neg_inf() { return __int_as_float(0xff800000); }
__device__ __forceinline__ float pos_inf() { return __int_as_float(0x7f800000); }

// ---------------- pairwise sq distances, DIFF FORM, symmetric halving ----------
// d[i][j] accumulated sequentially over c (bitwise == R12). Since
// fmaf(a-b,a-b,s) == fmaf(b-a,b-a,s) bitwise, d[j][i] = d[i][j] exactly:
// compute tiles by<=bx only, scatter transpose through smem staging.
__global__ __launch_bounds__(256, 2)
void dist_gemm(const float* __restrict__ h, int ld, int C) {
    if (blockIdx.y > blockIdx.x) return;
    __shared__ float As[8][132];
    __shared__ float Bs[8][132];
    __shared__ float Tst[32][132];
    int b   = blockIdx.z;
    const float* hb = h + (size_t)b * NPTS * ld;
    int tid = threadIdx.x;
    int tx = tid & 15, ty = tid >> 4;
    int m0 = blockIdx.y * 128, n0 = blockIdx.x * 128;
    int r  = tid >> 1, c4 = (tid & 1) * 4;

    float acc[8][8];
#pragma unroll
    for (int i = 0; i < 8; i++)
#pragma unroll
        for (int j = 0; j < 8; j++) acc[i][j] = 0.f;

    const float* Arow = hb + (size_t)(m0 + r) * ld;
    const float* Brow = hb + (size_t)(n0 + r) * ld;

    for (int k0 = 0; k0 < C; k0 += 8) {
#pragma unroll
        for (int j = 0; j < 4; j++) {
            int k = k0 + c4 + j;
            As[c4 + j][r] = (k < C) ? Arow[k] : 0.f;
            Bs[c4 + j][r] = (k < C) ? Brow[k] : 0.f;
        }
        __syncthreads();
#pragma unroll
        for (int k = 0; k < 8; k++) {
            float a[8], bb[8];
            *(float4*)(a)      = *(const float4*)&As[k][ty * 8];
            *(float4*)(a + 4)  = *(const float4*)&As[k][ty * 8 + 4];
            *(float4*)(bb)     = *(const float4*)&Bs[k][tx * 8];
            *(float4*)(bb + 4) = *(const float4*)&Bs[k][tx * 8 + 4];
#pragma unroll
            for (int i = 0; i < 8; i++)
#pragma unroll
                for (int j = 0; j < 8; j++) {
                    float d = a[i] - bb[j];
                    acc[i][j] = fmaf(d, d, acc[i][j]);
                }
        }
        __syncthreads();
    }

    float* dbase = g_dist + (size_t)b * NPTS * NPTS;
    // direct tile write
#pragma unroll
    for (int i = 0; i < 8; i++) {
        float* drow = dbase + (size_t)(m0 + ty * 8 + i) * NPTS;
#pragma unroll
        for (int jj = 0; jj < 2; jj++) {
            float4 v;
            v.x = acc[i][jj * 4 + 0];
            v.y = acc[i][jj * 4 + 1];
            v.z = acc[i][jj * 4 + 2];
            v.w = acc[i][jj * 4 + 3];
            *(float4*)&drow[n0 + tx * 8 + jj * 4] = v;
        }
    }
    // transposed tile write (off-diagonal only), staged for coalescing
    if (blockIdx.y != blockIdx.x) {
        __syncthreads();
        for (int c = 0; c < 4; c++) {
            if ((tx >> 2) == c) {
#pragma unroll
                for (int j = 0; j < 8; j++) {
                    int nl = (tx & 3) * 8 + j;
#pragma unroll
                    for (int i = 0; i < 8; i++)
                        Tst[nl][ty * 8 + i] = acc[i][j];
                }
            }
            __syncthreads();
            int nl2 = tid >> 3;
            int mc  = (tid & 7) * 16;
            float* dTrow = dbase + (size_t)(n0 + c * 32 + nl2) * NPTS + m0 + mc;
#pragma unroll
            for (int q = 0; q < 4; q++)
                *(float4*)&dTrow[q * 4] = *(const float4*)&Tst[nl2][mc + q * 4];
            __syncthreads();
        }
    }
}

// ---------------- warp-per-row top-K (UNCHANGED: bitwise-critical) -------------
__global__ void topk_kernel() {
    int gwarp = (blockIdx.x * blockDim.x + threadIdx.x) >> 5;
    int lane  = threadIdx.x & 31;
    if (gwarp >= BN_TOT) return;
    const float* drow = &g_dist[(size_t)gwarp * NPTS];

    float best[KNN];
    int   bidx[KNN];
#pragma unroll
    for (int i = 0; i < KNN; i++) { best[i] = pos_inf(); bidx[i] = -1; }

    for (int m = lane; m < NPTS; m += 32) {
        float d = drow[m];
        if (d < best[KNN - 1]) {
            int p = KNN - 1;
            while (p > 0 && best[p - 1] > d) {
                best[p] = best[p - 1]; bidx[p] = bidx[p - 1]; p--;
            }
            best[p] = d; bidx[p] = m;
        }
    }
    int ptr = 0;
    for (int s = 0; s < KNN; s++) {
        float v  = (ptr < KNN) ? best[ptr] : pos_inf();
        int   ci = (ptr < KNN) ? bidx[ptr] : -1;
        float mv = v; int ml = lane;
#pragma unroll
        for (int off = 16; off > 0; off >>= 1) {
            float ov = __shfl_down_sync(0xffffffffu, mv, off);
            int   ol = __shfl_down_sync(0xffffffffu, ml, off);
            if (ov < mv) { mv = ov; ml = ol; }
        }
        ml = __shfl_sync(0xffffffffu, ml, 0);
        int widx = __shfl_sync(0xffffffffu, ci, ml);
        if (lane == ml) ptr++;
        if (lane == 0) g_idx[gwarp * KNN + s] = widx;
    }
}

// ---------------- BN accumulators ----------------------------------------------
__global__ void zero_stats() {
    int t = threadIdx.x;
    if (t < 256) { g_sum[t] = 0.0; g_sumsq[t] = 0.0; }
}

// ---------------- fused edge-feature GEMM + stats ------------------------------
// A[m][k] = k<C ? h[nbr(m)][k]-h[ctr(m)][k] : h[ctr(m)][k-C]
// Same subtraction of same operands as the old edge_kernel, same sequential-k
// accumulation => h_pre bitwise identical to R12.
template<int TN>
__global__ __launch_bounds__(256, 2)
void edge_gemm(const float* __restrict__ h, int ld, int C,
               const float* __restrict__ W,
               const float* __restrict__ bias,
               float* __restrict__ Cmat, int O) {
    const int TILE_N = TN * 16;
    const int Kd = 2 * C;
    __shared__ float  As[8][132];
    __shared__ float  Bs[8][TILE_N + 4];
    __shared__ double sSum[TILE_N];
    __shared__ double sSq [TILE_N];

    int tid = threadIdx.x;
    int tx = tid & 15, ty = tid >> 4;
    int m0 = blockIdx.x * 128, n0 = blockIdx.y * TILE_N;
    int r  = tid >> 1, c4 = (tid & 1) * 4;

    if (tid < TILE_N) { sSum[tid] = 0.0; sSq[tid] = 0.0; }

    float acc[8][TN];
#pragma unroll
    for (int i = 0; i < 8; i++)
#pragma unroll
        for (int j = 0; j < TN; j++) acc[i][j] = 0.f;

    // per-row gather pointers (rows m0+r)
    int m   = m0 + r;
    int bn  = m / KNN;
    int b   = bn >> 11;
    int nbr = g_idx[m];
    const float* rowC = h + (size_t)bn * ld;
    const float* rowN = h + (size_t)((b << 11) + nbr) * ld;

    const float* Wrow = (tid < TILE_N * 2) ? (W + (size_t)(n0 + (tid >> 1)) * Kd) : W;
    int wk4 = (tid & 1) * 4;

    for (int k0 = 0; k0 < Kd; k0 += 8) {
#pragma unroll
        for (int j = 0; j < 4; j++) {
            int k = k0 + c4 + j;
            float v = 0.f;
            if (k < C)        v = rowN[k] - rowC[k];
            else if (k < Kd)  v = rowC[k - C];
            As[c4 + j][r] = v;
        }
        if (tid < TILE_N * 2) {
            int n = tid >> 1;
#pragma unroll
            for (int j = 0; j < 4; j++) {
                int k = k0 + wk4 + j;
                Bs[wk4 + j][n] = (k < Kd && (n0 + n) < O) ? Wrow[k] : 0.f;
            }
        }
        __syncthreads();
#pragma unroll
        for (int k = 0; k < 8; k++) {
            float a[8], bb[TN];
            *(float4*)(a)     = *(const float4*)&As[k][ty * 8];
            *(float4*)(a + 4) = *(const float4*)&As[k][ty * 8 + 4];
            *(float4*)(bb)    = *(const float4*)&Bs[k][tx * TN];
            if (TN == 8) *(float4*)(bb + 4) = *(const float4*)&Bs[k][tx * TN + 4];
#pragma unroll
            for (int i = 0; i < 8; i++)
#pragma unroll
                for (int j = 0; j < TN; j++)
                    acc[i][j] = fmaf(a[i], bb[j], acc[i][j]);
        }
        __syncthreads();
    }

#pragma unroll
    for (int j = 0; j < TN; j++) {
        int col = tx * TN + j;
        float bv = ((n0 + col) < O) ? bias[n0 + col] : 0.f;
        double ps = 0.0, pq = 0.0;
#pragma unroll
        for (int i = 0; i < 8; i++) {
            float v = acc[i][j] + bv;
            acc[i][j] = v;
            ps += (double)v;
            pq += (double)v * (double)v;
        }
        atomicAdd(&sSum[col], ps);
        atomicAdd(&sSq[col],  pq);
    }
#pragma unroll
    for (int i = 0; i < 8; i++) {
        float* crow = Cmat + (size_t)(m0 + ty * 8 + i) * O;
        if (n0 + tx * TN + TN - 1 < O) {
            *(float4*)&crow[n0 + tx * TN] = *(float4*)&acc[i][0];
            if (TN == 8) *(float4*)&crow[n0 + tx * TN + 4] = *(float4*)&acc[i][4];
        }
    }
    __syncthreads();
    if (tid < TILE_N && (n0 + tid) < O) {
        atomicAdd(&g_sum[n0 + tid],   sSum[tid]);
        atomicAdd(&g_sumsq[n0 + tid], sSq[tid]);
    }
}

// ---------------- plain tiled SGEMM for the final conv -------------------------
__global__ __launch_bounds__(256, 2)
void gemm_tile(const float* __restrict__ A, int lda,
               const float* __restrict__ W, int ldw,
               const float* __restrict__ bias,
               float* __restrict__ Cmat, int ldc,
               int Kd, int Nc) {
    __shared__ float As[8][132];
    __shared__ float Bs[8][132];
    int tid = threadIdx.x;
    int tx = tid & 15, ty = tid >> 4;
    int m0 = blockIdx.x * 128, n0 = blockIdx.y * 128;
    int r  = tid >> 1, c4 = (tid & 1) * 4;

    float acc[8][8];
#pragma unroll
    for (int i = 0; i < 8; i++)
#pragma unroll
        for (int j = 0; j < 8; j++) acc[i][j] = 0.f;

    const float* Arow = A + (size_t)(m0 + r) * lda;
    const float* Wrow = W + (size_t)(n0 + r) * ldw;

    for (int k0 = 0; k0 < Kd; k0 += 8) {
#pragma unroll
        for (int j = 0; j < 4; j++) {
            int k = k0 + c4 + j;
            As[c4 + j][r] = (k < Kd) ? Arow[k] : 0.f;
            Bs[c4 + j][r] = (k < Kd) ? Wrow[k] : 0.f;
        }
        __syncthreads();
#pragma unroll
        for (int k = 0; k < 8; k++) {
            float a[8], bb[8];
            *(float4*)(a)      = *(const float4*)&As[k][ty * 8];
            *(float4*)(a + 4)  = *(const float4*)&As[k][ty * 8 + 4];
            *(float4*)(bb)     = *(const float4*)&Bs[k][tx * 8];
            *(float4*)(bb + 4) = *(const float4*)&Bs[k][tx * 8 + 4];
#pragma unroll
            for (int i = 0; i < 8; i++)
#pragma unroll
                for (int j = 0; j < 8; j++)
                    acc[i][j] = fmaf(a[i], bb[j], acc[i][j]);
        }
        __syncthreads();
    }

#pragma unroll
    for (int i = 0; i < 8; i++) {
        float* crow = Cmat + (size_t)(m0 + ty * 8 + i) * ldc;
#pragma unroll
        for (int jj = 0; jj < 2; jj++) {
            int n = n0 + tx * 8 + jj * 4;
            float4 v;
            v.x = acc[i][jj * 4 + 0] + bias[n + 0];
            v.y = acc[i][jj * 4 + 1] + bias[n + 1];
            v.z = acc[i][jj * 4 + 2] + bias[n + 2];
            v.w = acc[i][jj * 4 + 3] + bias[n + 3];
            *(float4*)&crow[n] = v;
        }
    }
}

__global__ void finalize_stats(const float* __restrict__ gam,
                               const float* __restrict__ bet, int O, double cnt) {
    int o = blockIdx.x * blockDim.x + threadIdx.x;
    if (o >= O) return;
    double mean = g_sum[o] / cnt;
    double var  = g_sumsq[o] / cnt - mean * mean;
    float inv = rsqrtf((float)var + 1e-5f);
    float sc  = gam[o] * inv;
    g_scale[o] = sc;
    g_shift[o] = bet[o] - (float)mean * sc;
}

// ---------------- BN + LeakyReLU + max over k ---------------------------------
__global__ void bn_relu_max(int O, int outOff) {
    int t = blockIdx.x * blockDim.x + threadIdx.x;
    if (t >= BN_TOT * O) return;
    int o  = t % O;
    int bn = t / O;
    float sc = g_scale[o], sh = g_shift[o];
    float mx = neg_inf();
    size_t base = (size_t)bn * KNN * O + o;
#pragma unroll 5
    for (int k = 0; k < KNN; k++) {
        float v = g_hpre[base + (size_t)k * O];
        v = fmaf(v, sc, sh);
        v = (v >= 0.f) ? v : 0.2f * v;
        mx = fmaxf(mx, v);
    }
    g_xcat[(size_t)bn * LDCAT + outOff + o] = mx;
}

// ---------------- global max pool over N --------------------------------------
__global__ void max_over_n(float* __restrict__ out) {
    int t = blockIdx.x * blockDim.x + threadIdx.x;
    if (t >= BATCH * FIN_O) return;
    int o = t % FIN_O, b = t / FIN_O;
    const float* base = g_fin + (size_t)b * NPTS * FIN_O + o;
    float mx = neg_inf();
#pragma unroll 4
    for (int n = 0; n < NPTS; n++) mx = fmaxf(mx, base[(size_t)n * FIN_O]);
    out[t] = mx;
}

// ==============================================================================
extern "C" void kernel_launch(void* const* d_in, const int* in_sizes, int n_in,
                              void* d_out, int out_size) {
    const float* x = (const float*)d_in[0];
    const float* Wm[4], *bm[4], *gm[4], *bem[4];
    for (int i = 0; i < 4; i++) {
        Wm[i]  = (const float*)d_in[1 + 4 * i];
        bm[i]  = (const float*)d_in[2 + 4 * i];
        gm[i]  = (const float*)d_in[3 + 4 * i];
        bem[i] = (const float*)d_in[4 + 4 * i];
    }
    const float* Wf = (const float*)d_in[17];
    const float* bf = (const float*)d_in[18];
    float* out = (float*)d_out;

    float *hpre_ptr, *xcat_ptr, *fin_ptr;
    cudaGetSymbolAddress((void**)&hpre_ptr, g_hpre);
    cudaGetSymbolAddress((void**)&xcat_ptr, g_xcat);
    cudaGetSymbolAddress((void**)&fin_ptr,  g_fin);

    const int Hs[4]   = {64, 64, 128, 256};
    const int offs[4] = {0, 64, 128, 256};

    const float* hsrc = x;
    int ld = 3, C = 3;

    for (int i = 0; i < 4; i++) {
        int O = Hs[i];

        dist_gemm<<<dim3(NPTS / 128, NPTS / 128, BATCH), 256>>>(hsrc, ld, C);
        topk_kernel<<<BN_TOT / 8, 256>>>();
        zero_stats<<<1, 256>>>();

        if (O == 64) {
            edge_gemm<4><<<dim3(M_EDGES / 128, 1), 256>>>(
                hsrc, ld, C, Wm[i], bm[i], hpre_ptr, O);
        } else {
            edge_gemm<8><<<dim3(M_EDGES / 128, O / 128), 256>>>(
                hsrc, ld, C, Wm[i], bm[i], hpre_ptr, O);
        }

        finalize_stats<<<1, 256>>>(gm[i], bem[i], O, (double)M_EDGES);
        bn_relu_max<<<((size_t)BN_TOT * O + 255) / 256, 256>>>(O, offs[i]);

        hsrc = xcat_ptr + offs[i];
        ld = LDCAT;
        C  = O;
    }

    // final 1x1 conv (GEMM) + global max pool over N
    gemm_tile<<<dim3(BN_TOT / 128, FIN_O / 128), 256>>>(
        xcat_ptr, LDCAT, Wf, LDCAT, bf, fin_ptr, FIN_O, LDCAT, FIN_O);
    max_over_n<<<(BATCH * FIN_O + 255) / 256, 256>>>(out);
}

// round 14
// speedup vs baseline: 1.4232x; 1.0791x over previous
#include <cuda_runtime.h>
#include <cstdint>

#define BATCH 8
#define NPTS 2048
#define BN_TOT (BATCH * NPTS)          // 16384
#define KNN 20
#define M_EDGES (BN_TOT * KNN)         // 327680
#define LDCAT 512
#define FIN_O 1024

// ---------------- scratch (device globals; no allocations allowed) -------------
__device__ float  g_dist[(size_t)BATCH * NPTS * NPTS];   // 134MB
__device__ int    g_idx [M_EDGES];
__device__ float  g_hpre[(size_t)M_EDGES * 256];         // pre-BN conv out, max O=256
__device__ float  g_xcat[(size_t)BN_TOT * LDCAT];
__device__ float  g_fin [(size_t)BN_TOT * FIN_O];
__device__ double g_sum  [256];
__device__ double g_sumsq[256];
__device__ float  g_scale[256];
__device__ float  g_shift[256];

__device__ __forceinline__ float neg_inf() { return __int_as_float(0xff800000); }
__device__ __forceinline__ float pos_inf() { return __int_as_float(0x7f800000); }

// Vectorized loaders. All produce values bitwise-identical to the scalar forms
// they replace (float4 load + per-component arithmetic).
__device__ __forceinline__ void load_h4(const float* __restrict__ row, int kk,
                                        int C, bool al, float v[4]) {
    if (al && kk + 3 < C) {
        float4 t = *(const float4*)&row[kk];
        v[0] = t.x; v[1] = t.y; v[2] = t.z; v[3] = t.w;
    } else {
#pragma unroll
        for (int j = 0; j < 4; j++) { int k = kk + j; v[j] = (k < C) ? row[k] : 0.f; }
    }
}

__device__ __forceinline__ void load_edge4(const float* __restrict__ rowN,
                                           const float* __restrict__ rowC,
                                           int kk, int C, int Kd, bool al, float v[4]) {
    if (al && kk + 3 < C) {
        float4 n = *(const float4*)&rowN[kk];
        float4 c = *(const float4*)&rowC[kk];
        v[0] = n.x - c.x; v[1] = n.y - c.y; v[2] = n.z - c.z; v[3] = n.w - c.w;
    } else if (al && kk >= C && kk + 3 < Kd) {
        float4 c = *(const float4*)&rowC[kk - C];
        v[0] = c.x; v[1] = c.y; v[2] = c.z; v[3] = c.w;
    } else {
#pragma unroll
        for (int j = 0; j < 4; j++) {
            int k = kk + j; float t = 0.f;
            if (k < C)       t = rowN[k] - rowC[k];
            else if (k < Kd) t = rowC[k - C];
            v[j] = t;
        }
    }
}

// ---------------- pairwise sq distances, DIFF FORM, symmetric, double-buffered -
// d[i][j] accumulated sequentially over c => bitwise == R13.
__global__ __launch_bounds__(256, 2)
void dist_gemm(const float* __restrict__ h, int ld, int C) {
    if (blockIdx.y > blockIdx.x) return;
    __shared__ float As[2][8][132];
    __shared__ float Bs[2][8][132];
    __shared__ float Tst[32][132];
    int b   = blockIdx.z;
    const float* hb = h + (size_t)b * NPTS * ld;
    int tid = threadIdx.x;
    int tx = tid & 15, ty = tid >> 4;
    int m0 = blockIdx.y * 128, n0 = blockIdx.x * 128;
    int r  = tid >> 1, c4 = (tid & 1) * 4;
    bool al = ((ld & 3) == 0);

    float acc[8][8];
#pragma unroll
    for (int i = 0; i < 8; i++)
#pragma unroll
        for (int j = 0; j < 8; j++) acc[i][j] = 0.f;

    const float* Arow = hb + (size_t)(m0 + r) * ld;
    const float* Brow = hb + (size_t)(n0 + r) * ld;

    int ntiles = (C + 7) / 8;
    float apf[4], bpf[4];
    load_h4(Arow, c4, C, al, apf);
    load_h4(Brow, c4, C, al, bpf);
#pragma unroll
    for (int j = 0; j < 4; j++) { As[0][c4 + j][r] = apf[j]; Bs[0][c4 + j][r] = bpf[j]; }
    __syncthreads();

    for (int t = 0; t < ntiles; t++) {
        int p = t & 1;
        if (t + 1 < ntiles) {
            load_h4(Arow, (t + 1) * 8 + c4, C, al, apf);
            load_h4(Brow, (t + 1) * 8 + c4, C, al, bpf);
        }
#pragma unroll
        for (int k = 0; k < 8; k++) {
            float a[8], bb[8];
            *(float4*)(a)      = *(const float4*)&As[p][k][ty * 8];
            *(float4*)(a + 4)  = *(const float4*)&As[p][k][ty * 8 + 4];
            *(float4*)(bb)     = *(const float4*)&Bs[p][k][tx * 8];
            *(float4*)(bb + 4) = *(const float4*)&Bs[p][k][tx * 8 + 4];
#pragma unroll
            for (int i = 0; i < 8; i++)
#pragma unroll
                for (int j = 0; j < 8; j++) {
                    float d = a[i] - bb[j];
                    acc[i][j] = fmaf(d, d, acc[i][j]);
                }
        }
        if (t + 1 < ntiles) {
#pragma unroll
            for (int j = 0; j < 4; j++) {
                As[1 - p][c4 + j][r] = apf[j];
                Bs[1 - p][c4 + j][r] = bpf[j];
            }
            __syncthreads();
        }
    }

    float* dbase = g_dist + (size_t)b * NPTS * NPTS;
#pragma unroll
    for (int i = 0; i < 8; i++) {
        float* drow = dbase + (size_t)(m0 + ty * 8 + i) * NPTS;
#pragma unroll
        for (int jj = 0; jj < 2; jj++) {
            float4 v;
            v.x = acc[i][jj * 4 + 0];
            v.y = acc[i][jj * 4 + 1];
            v.z = acc[i][jj * 4 + 2];
            v.w = acc[i][jj * 4 + 3];
            *(float4*)&drow[n0 + tx * 8 + jj * 4] = v;
        }
    }
    // transposed tile (bitwise symmetric), staged for coalescing
    if (blockIdx.y != blockIdx.x) {
        __syncthreads();
        for (int c = 0; c < 4; c++) {
            if ((tx >> 2) == c) {
#pragma unroll
                for (int j = 0; j < 8; j++) {
                    int nl = (tx & 3) * 8 + j;
#pragma unroll
                    for (int i = 0; i < 8; i++)
                        Tst[nl][ty * 8 + i] = acc[i][j];
                }
            }
            __syncthreads();
            int nl2 = tid >> 3;
            int mc  = (tid & 7) * 16;
            float* dTrow = dbase + (size_t)(n0 + c * 32 + nl2) * NPTS + m0 + mc;
#pragma unroll
            for (int q = 0; q < 4; q++)
                *(float4*)&dTrow[q * 4] = *(const float4*)&Tst[nl2][mc + q * 4];
            __syncthreads();
        }
    }
}

// ---------------- warp-per-row top-K (UNCHANGED: bitwise-critical) -------------
__global__ void topk_kernel() {
    int gwarp = (blockIdx.x * blockDim.x + threadIdx.x) >> 5;
    int lane  = threadIdx.x & 31;
    if (gwarp >= BN_TOT) return;
    const float* drow = &g_dist[(size_t)gwarp * NPTS];

    float best[KNN];
    int   bidx[KNN];
#pragma unroll
    for (int i = 0; i < KNN; i++) { best[i] = pos_inf(); bidx[i] = -1; }

    for (int m = lane; m < NPTS; m += 32) {
        float d = drow[m];
        if (d < best[KNN - 1]) {
            int p = KNN - 1;
            while (p > 0 && best[p - 1] > d) {
                best[p] = best[p - 1]; bidx[p] = bidx[p - 1]; p--;
            }
            best[p] = d; bidx[p] = m;
        }
    }
    int ptr = 0;
    for (int s = 0; s < KNN; s++) {
        float v  = (ptr < KNN) ? best[ptr] : pos_inf();
        int   ci = (ptr < KNN) ? bidx[ptr] : -1;
        float mv = v; int ml = lane;
#pragma unroll
        for (int off = 16; off > 0; off >>= 1) {
            float ov = __shfl_down_sync(0xffffffffu, mv, off);
            int   ol = __shfl_down_sync(0xffffffffu, ml, off);
            if (ov < mv) { mv = ov; ml = ol; }
        }
        ml = __shfl_sync(0xffffffffu, ml, 0);
        int widx = __shfl_sync(0xffffffffu, ci, ml);
        if (lane == ml) ptr++;
        if (lane == 0) g_idx[gwarp * KNN + s] = widx;
    }
}

// ---------------- BN accumulators ----------------------------------------------
__global__ void zero_stats() {
    int t = threadIdx.x;
    if (t < 256) { g_sum[t] = 0.0; g_sumsq[t] = 0.0; }
}

// ---------------- fused edge-feature GEMM + stats, double-buffered -------------
// A[m][k] = k<C ? h[nbr][k]-h[ctr][k] : h[ctr][k-C]; sequential-k accumulation
// => h_pre bitwise identical to R13.
template<int TN>
__global__ __launch_bounds__(256, 2)
void edge_gemm(const float* __restrict__ h, int ld, int C,
               const float* __restrict__ W,
               const float* __restrict__ bias,
               float* __restrict__ Cmat, int O) {
    const int TILE_N = TN * 16;
    const int Kd = 2 * C;
    __shared__ float  As[2][8][132];
    __shared__ float  Bs[2][8][TILE_N + 4];
    __shared__ double sSum[TILE_N];
    __shared__ double sSq [TILE_N];

    int tid = threadIdx.x;
    int tx = tid & 15, ty = tid >> 4;
    int m0 = blockIdx.x * 128, n0 = blockIdx.y * TILE_N;
    int r  = tid >> 1, c4 = (tid & 1) * 4;
    bool al  = ((ld & 3) == 0);          // h rows float4-able (layers 2-4)
    bool wal = ((Kd & 3) == 0);          // W rows float4-able

    if (tid < TILE_N) { sSum[tid] = 0.0; sSq[tid] = 0.0; }

    float acc[8][TN];
#pragma unroll
    for (int i = 0; i < 8; i++)
#pragma unroll
        for (int j = 0; j < TN; j++) acc[i][j] = 0.f;

    int m   = m0 + r;
    int bn  = m / KNN;
    int b   = bn >> 11;
    int nbr = g_idx[m];
    const float* rowC = h + (size_t)bn * ld;
    const float* rowN = h + (size_t)((b << 11) + nbr) * ld;

    bool wload = (tid < TILE_N * 2);
    int  nw    = tid >> 1;
    const float* Wrow = wload ? (W + (size_t)(n0 + nw) * Kd) : W;
    int wk4 = (tid & 1) * 4;

    int ntiles = (Kd + 7) / 8;
    float apf[4], wpf[4];
    load_edge4(rowN, rowC, c4, C, Kd, al, apf);
    if (wload) {
        if (wal && wk4 + 3 < Kd) {
            float4 t = *(const float4*)&Wrow[wk4];
            wpf[0] = t.x; wpf[1] = t.y; wpf[2] = t.z; wpf[3] = t.w;
        } else {
#pragma unroll
            for (int j = 0; j < 4; j++) wpf[j] = (wk4 + j < Kd) ? Wrow[wk4 + j] : 0.f;
        }
    }
#pragma unroll
    for (int j = 0; j < 4; j++) As[0][c4 + j][r] = apf[j];
    if (wload) {
#pragma unroll
        for (int j = 0; j < 4; j++) Bs[0][wk4 + j][nw] = wpf[j];
    }
    __syncthreads();

    for (int t = 0; t < ntiles; t++) {
        int p = t & 1;
        if (t + 1 < ntiles) {
            int k0 = (t + 1) * 8;
            load_edge4(rowN, rowC, k0 + c4, C, Kd, al, apf);
            if (wload) {
                if (wal && k0 + wk4 + 3 < Kd) {
                    float4 tt = *(const float4*)&Wrow[k0 + wk4];
                    wpf[0] = tt.x; wpf[1] = tt.y; wpf[2] = tt.z; wpf[3] = tt.w;
                } else {
#pragma unroll
                    for (int j = 0; j < 4; j++)
                        wpf[j] = (k0 + wk4 + j < Kd) ? Wrow[k0 + wk4 + j] : 0.f;
                }
            }
        }
#pragma unroll
        for (int k = 0; k < 8; k++) {
            float a[8], bb[TN];
            *(float4*)(a)     = *(const float4*)&As[p][k][ty * 8];
            *(float4*)(a + 4) = *(const float4*)&As[p][k][ty * 8 + 4];
            *(float4*)(bb)    = *(const float4*)&Bs[p][k][tx * TN];
            if (TN == 8) *(float4*)(bb + 4) = *(const float4*)&Bs[p][k][tx * TN + 4];
#pragma unroll
            for (int i = 0; i < 8; i++)
#pragma unroll
                for (int j = 0; j < TN; j++)
                    acc[i][j] = fmaf(a[i], bb[j], acc[i][j]);
        }
        if (t + 1 < ntiles) {
#pragma unroll
            for (int j = 0; j < 4; j++) As[1 - p][c4 + j][r] = apf[j];
            if (wload) {
#pragma unroll
                for (int j = 0; j < 4; j++) Bs[1 - p][wk4 + j][nw] = wpf[j];
            }
            __syncthreads();
        }
    }

#pragma unroll
    for (int j = 0; j < TN; j++) {
        int col = tx * TN + j;
        float bv = ((n0 + col) < O) ? bias[n0 + col] : 0.f;
        double ps = 0.0, pq = 0.0;
#pragma unroll
        for (int i = 0; i < 8; i++) {
            float v = acc[i][j] + bv;
            acc[i][j] = v;
            ps += (double)v;
            pq += (double)v * (double)v;
        }
        atomicAdd(&sSum[col], ps);
        atomicAdd(&sSq[col],  pq);
    }
#pragma unroll
    for (int i = 0; i < 8; i++) {
        float* crow = Cmat + (size_t)(m0 + ty * 8 + i) * O;
        if (n0 + tx * TN + TN - 1 < O) {
            *(float4*)&crow[n0 + tx * TN] = *(float4*)&acc[i][0];
            if (TN == 8) *(float4*)&crow[n0 + tx * TN + 4] = *(float4*)&acc[i][4];
        }
    }
    __syncthreads();
    if (tid < TILE_N && (n0 + tid) < O) {
        atomicAdd(&g_sum[n0 + tid],   sSum[tid]);
        atomicAdd(&g_sumsq[n0 + tid], sSq[tid]);
    }
}

// ---------------- plain tiled SGEMM for the final conv, double-buffered --------
__global__ __launch_bounds__(256, 2)
void gemm_tile(const float* __restrict__ A, int lda,
               const float* __restrict__ W, int ldw,
               const float* __restrict__ bias,
               float* __restrict__ Cmat, int ldc,
               int Kd, int Nc) {
    __shared__ float As[2][8][132];
    __shared__ float Bs[2][8][132];
    int tid = threadIdx.x;
    int tx = tid & 15, ty = tid >> 4;
    int m0 = blockIdx.x * 128, n0 = blockIdx.y * 128;
    int r  = tid >> 1, c4 = (tid & 1) * 4;

    float acc[8][8];
#pragma unroll
    for (int i = 0; i < 8; i++)
#pragma unroll
        for (int j = 0; j < 8; j++) acc[i][j] = 0.f;

    const float* Arow = A + (size_t)(m0 + r) * lda;
    const float* Wrow = W + (size_t)(n0 + r) * ldw;

    int ntiles = Kd / 8;
    float apf[4], wpf[4];
    load_h4(Arow, c4, Kd, true, apf);
    load_h4(Wrow, c4, Kd, true, wpf);
#pragma unroll
    for (int j = 0; j < 4; j++) { As[0][c4 + j][r] = apf[j]; Bs[0][c4 + j][r] = wpf[j]; }
    __syncthreads();

    for (int t = 0; t < ntiles; t++) {
        int p = t & 1;
        if (t + 1 < ntiles) {
            load_h4(Arow, (t + 1) * 8 + c4, Kd, true, apf);
            load_h4(Wrow, (t + 1) * 8 + c4, Kd, true, wpf);
        }
#pragma unroll
        for (int k = 0; k < 8; k++) {
            float a[8], bb[8];
            *(float4*)(a)      = *(const float4*)&As[p][k][ty * 8];
            *(float4*)(a + 4)  = *(const float4*)&As[p][k][ty * 8 + 4];
            *(float4*)(bb)     = *(const float4*)&Bs[p][k][tx * 8];
            *(float4*)(bb + 4) = *(const float4*)&Bs[p][k][tx * 8 + 4];
#pragma unroll
            for (int i = 0; i < 8; i++)
#pragma unroll
                for (int j = 0; j < 8; j++)
                    acc[i][j] = fmaf(a[i], bb[j], acc[i][j]);
        }
        if (t + 1 < ntiles) {
#pragma unroll
            for (int j = 0; j < 4; j++) {
                As[1 - p][c4 + j][r] = apf[j];
                Bs[1 - p][c4 + j][r] = wpf[j];
            }
            __syncthreads();
        }
    }

#pragma unroll
    for (int i = 0; i < 8; i++) {
        float* crow = Cmat + (size_t)(m0 + ty * 8 + i) * ldc;
#pragma unroll
        for (int jj = 0; jj < 2; jj++) {
            int n = n0 + tx * 8 + jj * 4;
            float4 v;
            v.x = acc[i][jj * 4 + 0] + bias[n + 0];
            v.y = acc[i][jj * 4 + 1] + bias[n + 1];
            v.z = acc[i][jj * 4 + 2] + bias[n + 2];
            v.w = acc[i][jj * 4 + 3] + bias[n + 3];
            *(float4*)&crow[n] = v;
        }
    }
}

__global__ void finalize_stats(const float* __restrict__ gam,
                               const float* __restrict__ bet, int O, double cnt) {
    int o = blockIdx.x * blockDim.x + threadIdx.x;
    if (o >= O) return;
    double mean = g_sum[o] / cnt;
    double var  = g_sumsq[o] / cnt - mean * mean;
    float inv = rsqrtf((float)var + 1e-5f);
    float sc  = gam[o] * inv;
    g_scale[o] = sc;
    g_shift[o] = bet[o] - (float)mean * sc;
}

// ---------------- BN + LeakyReLU + max over k ---------------------------------
__global__ void bn_relu_max(int O, int outOff) {
    int t = blockIdx.x * blockDim.x + threadIdx.x;
    if (t >= BN_TOT * O) return;
    int o  = t % O;
    int bn = t / O;
    float sc = g_scale[o], sh = g_shift[o];
    float mx = neg_inf();
    size_t base = (size_t)bn * KNN * O + o;
#pragma unroll 5
    for (int k = 0; k < KNN; k++) {
        float v = g_hpre[base + (size_t)k * O];
        v = fmaf(v, sc, sh);
        v = (v >= 0.f) ? v : 0.2f * v;
        mx = fmaxf(mx, v);
    }
    g_xcat[(size_t)bn * LDCAT + outOff + o] = mx;
}

// ---------------- global max pool over N --------------------------------------
__global__ void max_over_n(float* __restrict__ out) {
    int t = blockIdx.x * blockDim.x + threadIdx.x;
    if (t >= BATCH * FIN_O) return;
    int o = t % FIN_O, b = t / FIN_O;
    const float* base = g_fin + (size_t)b * NPTS * FIN_O + o;
    float mx = neg_inf();
#pragma unroll 4
    for (int n = 0; n < NPTS; n++) mx = fmaxf(mx, base[(size_t)n * FIN_O]);
    out[t] = mx;
}

// ==============================================================================
extern "C" void kernel_launch(void* const* d_in, const int* in_sizes, int n_in,
                              void* d_out, int out_size) {
    const float* x = (const float*)d_in[0];
    const float* Wm[4], *bm[4], *gm[4], *bem[4];
    for (int i = 0; i < 4; i++) {
        Wm[i]  = (const float*)d_in[1 + 4 * i];
        bm[i]  = (const float*)d_in[2 + 4 * i];
        gm[i]  = (const float*)d_in[3 + 4 * i];
        bem[i] = (const float*)d_in[4 + 4 * i];
    }
    const float* Wf = (const float*)d_in[17];
    const float* bf = (const float*)d_in[18];
    float* out = (float*)d_out;

    float *hpre_ptr, *xcat_ptr, *fin_ptr;
    cudaGetSymbolAddress((void**)&hpre_ptr, g_hpre);
    cudaGetSymbolAddress((void**)&xcat_ptr, g_xcat);
    cudaGetSymbolAddress((void**)&fin_ptr,  g_fin);

    const int Hs[4]   = {64, 64, 128, 256};
    const int offs[4] = {0, 64, 128, 256};

    const float* hsrc = x;
    int ld = 3, C = 3;

    for (int i = 0; i < 4; i++) {
        int O = Hs[i];

        dist_gemm<<<dim3(NPTS / 128, NPTS / 128, BATCH), 256>>>(hsrc, ld, C);
        topk_kernel<<<BN_TOT / 8, 256>>>();
        zero_stats<<<1, 256>>>();

        if (O == 64) {
            edge_gemm<4><<<dim3(M_EDGES / 128, 1), 256>>>(
                hsrc, ld, C, Wm[i], bm[i], hpre_ptr, O);
        } else {
            edge_gemm<8><<<dim3(M_EDGES / 128, O / 128), 256>>>(
                hsrc, ld, C, Wm[i], bm[i], hpre_ptr, O);
        }

        finalize_stats<<<1, 256>>>(gm[i], bem[i], O, (double)M_EDGES);
        bn_relu_max<<<((size_t)BN_TOT * O + 255) / 256, 256>>>(O, offs[i]);

        hsrc = xcat_ptr + offs[i];
        ld = LDCAT;
        C  = O;
    }

    // final 1x1 conv (GEMM) + global max pool over N
    gemm_tile<<<dim3(BN_TOT / 128, FIN_O / 128), 256>>>(
        xcat_ptr, LDCAT, Wf, LDCAT, bf, fin_ptr, FIN_O, LDCAT, FIN_O);
    max_over_n<<<(BATCH * FIN_O + 255) / 256, 256>>>(out);
}

// round 15
// speedup vs baseline: 1.5130x; 1.0631x over previous
#include <cuda_runtime.h>
#include <cstdint>

#define BATCH 8
#define NPTS 2048
#define BN_TOT (BATCH * NPTS)          // 16384
#define KNN 20
#define M_EDGES (BN_TOT * KNN)         // 327680
#define LDCAT 512
#define FIN_O 1024

// ---------------- scratch (device globals; no allocations allowed) -------------
__device__ float  g_dist[(size_t)BATCH * NPTS * NPTS];   // 134MB
__device__ int    g_idx [M_EDGES];
__device__ float  g_hpre[(size_t)M_EDGES * 256];         // pre-BN conv out, max O=256
__device__ float  g_xcat[(size_t)BN_TOT * LDCAT];
__device__ float  g_fin [(size_t)BN_TOT * FIN_O];
__device__ double g_sum  [256];
__device__ double g_sumsq[256];
__device__ float  g_scale[256];
__device__ float  g_shift[256];

__device__ __forceinline__ float neg_inf() { return __int_as_float(0xff800000); }
__device__ __forceinline__ float pos_inf() { return __int_as_float(0x7f800000); }

// Vectorized loaders; values bitwise-identical to scalar forms.
__device__ __forceinline__ void load_h4(const float* __restrict__ row, int kk,
                                        int C, bool al, float v[4]) {
    if (al && kk + 3 < C) {
        float4 t = *(const float4*)&row[kk];
        v[0] = t.x; v[1] = t.y; v[2] = t.z; v[3] = t.w;
    } else {
#pragma unroll
        for (int j = 0; j < 4; j++) { int k = kk + j; v[j] = (k < C) ? row[k] : 0.f; }
    }
}

__device__ __forceinline__ void load_edge4(const float* __restrict__ rowN,
                                           const float* __restrict__ rowC,
                                           int kk, int C, int Kd, bool al, float v[4]) {
    if (al && kk + 3 < C) {
        float4 n = *(const float4*)&rowN[kk];
        float4 c = *(const float4*)&rowC[kk];
        v[0] = n.x - c.x; v[1] = n.y - c.y; v[2] = n.z - c.z; v[3] = n.w - c.w;
    } else if (al && kk >= C && kk + 3 < Kd) {
        float4 c = *(const float4*)&rowC[kk - C];
        v[0] = c.x; v[1] = c.y; v[2] = c.z; v[3] = c.w;
    } else {
#pragma unroll
        for (int j = 0; j < 4; j++) {
            int k = kk + j; float t = 0.f;
            if (k < C)       t = rowN[k] - rowC[k];
            else if (k < Kd) t = rowC[k - C];
            v[j] = t;
        }
    }
}

// ---------------- pairwise sq distances, DIFF FORM, symmetric, KTILE=16 --------
// d[i][j] accumulated sequentially over c => bitwise == R14.
__global__ __launch_bounds__(256, 2)
void dist_gemm(const float* __restrict__ h, int ld, int C) {
    if (blockIdx.y > blockIdx.x) return;
    __shared__ __align__(16) float As[2][16][132];
    __shared__ __align__(16) float Bs[2][16][132];
    int b   = blockIdx.z;
    const float* hb = h + (size_t)b * NPTS * ld;
    int tid = threadIdx.x;
    int tx = tid & 15, ty = tid >> 4;
    int m0 = blockIdx.y * 128, n0 = blockIdx.x * 128;
    int r  = tid >> 1, ks = (tid & 1) * 8;
    bool al = ((ld & 3) == 0);

    float acc[8][8];
#pragma unroll
    for (int i = 0; i < 8; i++)
#pragma unroll
        for (int j = 0; j < 8; j++) acc[i][j] = 0.f;

    const float* Arow = hb + (size_t)(m0 + r) * ld;
    const float* Brow = hb + (size_t)(n0 + r) * ld;

    int ntiles = (C + 15) / 16;
    float apf[8], bpf[8];
    load_h4(Arow, ks,     C, al, apf);
    load_h4(Arow, ks + 4, C, al, apf + 4);
    load_h4(Brow, ks,     C, al, bpf);
    load_h4(Brow, ks + 4, C, al, bpf + 4);
#pragma unroll
    for (int j = 0; j < 8; j++) { As[0][ks + j][r] = apf[j]; Bs[0][ks + j][r] = bpf[j]; }
    __syncthreads();

    for (int t = 0; t < ntiles; t++) {
        int p = t & 1;
        if (t + 1 < ntiles) {
            int k0 = (t + 1) * 16;
            load_h4(Arow, k0 + ks,     C, al, apf);
            load_h4(Arow, k0 + ks + 4, C, al, apf + 4);
            load_h4(Brow, k0 + ks,     C, al, bpf);
            load_h4(Brow, k0 + ks + 4, C, al, bpf + 4);
        }
#pragma unroll
        for (int k = 0; k < 16; k++) {
            float a[8], bb[8];
            *(float4*)(a)      = *(const float4*)&As[p][k][ty * 8];
            *(float4*)(a + 4)  = *(const float4*)&As[p][k][ty * 8 + 4];
            *(float4*)(bb)     = *(const float4*)&Bs[p][k][tx * 8];
            *(float4*)(bb + 4) = *(const float4*)&Bs[p][k][tx * 8 + 4];
#pragma unroll
            for (int i = 0; i < 8; i++)
#pragma unroll
                for (int j = 0; j < 8; j++) {
                    float d = a[i] - bb[j];
                    acc[i][j] = fmaf(d, d, acc[i][j]);
                }
        }
        if (t + 1 < ntiles) {
#pragma unroll
            for (int j = 0; j < 8; j++) {
                As[1 - p][ks + j][r] = apf[j];
                Bs[1 - p][ks + j][r] = bpf[j];
            }
            __syncthreads();
        }
    }

    float* dbase = g_dist + (size_t)b * NPTS * NPTS;
#pragma unroll
    for (int i = 0; i < 8; i++) {
        float* drow = dbase + (size_t)(m0 + ty * 8 + i) * NPTS;
#pragma unroll
        for (int jj = 0; jj < 2; jj++) {
            float4 v;
            v.x = acc[i][jj * 4 + 0];
            v.y = acc[i][jj * 4 + 1];
            v.z = acc[i][jj * 4 + 2];
            v.w = acc[i][jj * 4 + 3];
            *(float4*)&drow[n0 + tx * 8 + jj * 4] = v;
        }
    }
    // transposed tile (bitwise symmetric), staged in reused As buffer
    if (blockIdx.y != blockIdx.x) {
        __syncthreads();
        float (*Tst)[132] = (float(*)[132])&As[0][0][0];   // 32x132 fits in As
        for (int c = 0; c < 4; c++) {
            if ((tx >> 2) == c) {
#pragma unroll
                for (int j = 0; j < 8; j++) {
                    int nl = (tx & 3) * 8 + j;
#pragma unroll
                    for (int i = 0; i < 8; i++)
                        Tst[nl][ty * 8 + i] = acc[i][j];
                }
            }
            __syncthreads();
            int nl2 = tid >> 3;
            int mc  = (tid & 7) * 16;
            float* dTrow = dbase + (size_t)(n0 + c * 32 + nl2) * NPTS + m0 + mc;
#pragma unroll
            for (int q = 0; q < 4; q++)
                *(float4*)&dTrow[q * 4] = *(const float4*)&Tst[nl2][mc + q * 4];
            __syncthreads();
        }
    }
}

// ---------------- warp-per-row top-K (UNCHANGED: bitwise-critical) -------------
__global__ void topk_kernel() {
    int gwarp = (blockIdx.x * blockDim.x + threadIdx.x) >> 5;
    int lane  = threadIdx.x & 31;
    if (gwarp >= BN_TOT) return;
    const float* drow = &g_dist[(size_t)gwarp * NPTS];

    float best[KNN];
    int   bidx[KNN];
#pragma unroll
    for (int i = 0; i < KNN; i++) { best[i] = pos_inf(); bidx[i] = -1; }

    for (int m = lane; m < NPTS; m += 32) {
        float d = drow[m];
        if (d < best[KNN - 1]) {
            int p = KNN - 1;
            while (p > 0 && best[p - 1] > d) {
                best[p] = best[p - 1]; bidx[p] = bidx[p - 1]; p--;
            }
            best[p] = d; bidx[p] = m;
        }
    }
    int ptr = 0;
    for (int s = 0; s < KNN; s++) {
        float v  = (ptr < KNN) ? best[ptr] : pos_inf();
        int   ci = (ptr < KNN) ? bidx[ptr] : -1;
        float mv = v; int ml = lane;
#pragma unroll
        for (int off = 16; off > 0; off >>= 1) {
            float ov = __shfl_down_sync(0xffffffffu, mv, off);
            int   ol = __shfl_down_sync(0xffffffffu, ml, off);
            if (ov < mv) { mv = ov; ml = ol; }
        }
        ml = __shfl_sync(0xffffffffu, ml, 0);
        int widx = __shfl_sync(0xffffffffu, ci, ml);
        if (lane == ml) ptr++;
        if (lane == 0) g_idx[gwarp * KNN + s] = widx;
    }
}

// ---------------- BN accumulators ----------------------------------------------
__global__ void zero_stats() {
    int t = threadIdx.x;
    if (t < 256) { g_sum[t] = 0.0; g_sumsq[t] = 0.0; }
}

// ---------------- layer-1 specialized edge conv (C=3, Kd=6, O=64) --------------
// Same fmaf chain k=0..5 as the GEMM (its k=6,7 zero-pad fmas are exact no-ops)
// => h_pre bitwise identical. Stats: staged smem partials + 64 global atomics.
__global__ __launch_bounds__(256, 4)
void edge1_kernel(const float* __restrict__ h,
                  const float* __restrict__ W,
                  const float* __restrict__ bias,
                  float* __restrict__ Cmat) {
    __shared__ float  sW[64][8];
    __shared__ float  sA[64][6];
    __shared__ float  sB[64];
    __shared__ double sPS[4][64];
    __shared__ double sPQ[4][64];
    int tid = threadIdx.x;
    if (tid < 64) sB[tid] = bias[tid];
    for (int i = tid; i < 64 * 6; i += 256) sW[i / 6][i % 6] = W[i];
    if (tid < 64) {
        int m  = blockIdx.x * 64 + tid;
        int bn = m / KNN;
        int b  = bn >> 11;
        int nbr = g_idx[m];
        const float* rc = h + (size_t)bn * 3;
        const float* rn = h + (size_t)((b << 11) + nbr) * 3;
        sA[tid][0] = rn[0] - rc[0];
        sA[tid][1] = rn[1] - rc[1];
        sA[tid][2] = rn[2] - rc[2];
        sA[tid][3] = rc[0];
        sA[tid][4] = rc[1];
        sA[tid][5] = rc[2];
    }
    __syncthreads();
    int o  = tid & 63;
    int eg = tid >> 6;    // 0..3
    float w0 = sW[o][0], w1 = sW[o][1], w2 = sW[o][2];
    float w3 = sW[o][3], w4 = sW[o][4], w5 = sW[o][5];
    float bv = sB[o];
    double ps = 0.0, pq = 0.0;
    size_t base = (size_t)blockIdx.x * 64;
#pragma unroll
    for (int e0 = 0; e0 < 64; e0 += 4) {
        int e = e0 + eg;
        float acc = 0.f;
        acc = fmaf(sA[e][0], w0, acc);
        acc = fmaf(sA[e][1], w1, acc);
        acc = fmaf(sA[e][2], w2, acc);
        acc = fmaf(sA[e][3], w3, acc);
        acc = fmaf(sA[e][4], w4, acc);
        acc = fmaf(sA[e][5], w5, acc);
        float v = acc + bv;
        Cmat[(base + e) * 64 + o] = v;
        ps += (double)v;
        pq += (double)v * (double)v;
    }
    sPS[eg][o] = ps;
    sPQ[eg][o] = pq;
    __syncthreads();
    if (tid < 64) {
        double s = sPS[0][tid] + sPS[1][tid] + sPS[2][tid] + sPS[3][tid];
        double q = sPQ[0][tid] + sPQ[1][tid] + sPQ[2][tid] + sPQ[3][tid];
        atomicAdd(&g_sum[tid],   s);
        atomicAdd(&g_sumsq[tid], q);
    }
}

// ---------------- fused edge-feature GEMM + stats, KTILE=16, atomic-free -------
template<int TN>
__global__ __launch_bounds__(256, 2)
void edge_gemm(const float* __restrict__ h, int ld, int C,
               const float* __restrict__ W,
               const float* __restrict__ bias,
               float* __restrict__ Cmat, int O) {
    const int TILE_N = TN * 16;
    const int WN = (TN == 8) ? 8 : 4;
    const int Kd = 2 * C;
    __shared__ __align__(16) float As[2][16][132];
    __shared__ __align__(16) float Bs[2][16][TILE_N + 4];

    int tid = threadIdx.x;
    int tx = tid & 15, ty = tid >> 4;
    int m0 = blockIdx.x * 128, n0 = blockIdx.y * TILE_N;
    int r  = tid >> 1, ks = (tid & 1) * 8;
    bool al = ((ld & 3) == 0);

    float acc[8][TN];
#pragma unroll
    for (int i = 0; i < 8; i++)
#pragma unroll
        for (int j = 0; j < TN; j++) acc[i][j] = 0.f;

    int m   = m0 + r;
    int bn  = m / KNN;
    int b   = bn >> 11;
    int nbr = g_idx[m];
    const float* rowC = h + (size_t)bn * ld;
    const float* rowN = h + (size_t)((b << 11) + nbr) * ld;

    int nw = (TN == 8) ? (tid >> 1) : (tid >> 2);
    int wk = (TN == 8) ? ((tid & 1) * 8) : ((tid & 3) * 4);
    bool wok = (n0 + nw) < O;
    const float* Wrow = W + (size_t)(n0 + nw) * Kd;

    int ntiles = (Kd + 15) / 16;
    float apf[8], wpf[8];
    load_edge4(rowN, rowC, ks,     C, Kd, al, apf);
    load_edge4(rowN, rowC, ks + 4, C, Kd, al, apf + 4);
    if (wok) {
        *(float4*)wpf = *(const float4*)&Wrow[wk];
        if (WN == 8) *(float4*)(wpf + 4) = *(const float4*)&Wrow[wk + 4];
    } else {
#pragma unroll
        for (int j = 0; j < WN; j++) wpf[j] = 0.f;
    }
#pragma unroll
    for (int j = 0; j < 8; j++) As[0][ks + j][r] = apf[j];
#pragma unroll
    for (int j = 0; j < WN; j++) Bs[0][wk + j][nw] = wpf[j];
    __syncthreads();

    for (int t = 0; t < ntiles; t++) {
        int p = t & 1;
        if (t + 1 < ntiles) {
            int k0 = (t + 1) * 16;
            load_edge4(rowN, rowC, k0 + ks,     C, Kd, al, apf);
            load_edge4(rowN, rowC, k0 + ks + 4, C, Kd, al, apf + 4);
            if (wok) {
                *(float4*)wpf = *(const float4*)&Wrow[k0 + wk];
                if (WN == 8) *(float4*)(wpf + 4) = *(const float4*)&Wrow[k0 + wk + 4];
            }
        }
#pragma unroll
        for (int k = 0; k < 16; k++) {
            float a[8], bb[TN];
            *(float4*)(a)     = *(const float4*)&As[p][k][ty * 8];
            *(float4*)(a + 4) = *(const float4*)&As[p][k][ty * 8 + 4];
            *(float4*)(bb)    = *(const float4*)&Bs[p][k][tx * TN];
            if (TN == 8) *(float4*)(bb + 4) = *(const float4*)&Bs[p][k][tx * TN + 4];
#pragma unroll
            for (int i = 0; i < 8; i++)
#pragma unroll
                for (int j = 0; j < TN; j++)
                    acc[i][j] = fmaf(a[i], bb[j], acc[i][j]);
        }
        if (t + 1 < ntiles) {
#pragma unroll
            for (int j = 0; j < 8; j++) As[1 - p][ks + j][r] = apf[j];
#pragma unroll
            for (int j = 0; j < WN; j++) Bs[1 - p][wk + j][nw] = wpf[j];
            __syncthreads();
        }
    }

    // ---- epilogue: bias, stats via shfl + staged smem (no smem atomics) ----
    __syncthreads();                       // As/Bs free for reuse
    double* sPS = (double*)&As[0][0][0];   // [8][TILE_N] partial sums
    double* sPQ = (double*)&Bs[0][0][0];   // [8][TILE_N] partial sumsq
    int w = tid >> 5, lane = tid & 31;
#pragma unroll
    for (int j = 0; j < TN; j++) {
        int col = tx * TN + j;
        float bv = ((n0 + col) < O) ? bias[n0 + col] : 0.f;
        double ps = 0.0, pq = 0.0;
#pragma unroll
        for (int i = 0; i < 8; i++) {
            float v = acc[i][j] + bv;
            acc[i][j] = v;
            ps += (double)v;
            pq += (double)v * (double)v;
        }
        ps += __shfl_xor_sync(0xffffffffu, ps, 16);   // lanes L, L+16 share col
        pq += __shfl_xor_sync(0xffffffffu, pq, 16);
        if (lane < 16) { sPS[w * TILE_N + col] = ps; sPQ[w * TILE_N + col] = pq; }
    }
#pragma unroll
    for (int i = 0; i < 8; i++) {
        float* crow = Cmat + (size_t)(m0 + ty * 8 + i) * O;
        if (n0 + tx * TN + TN - 1 < O) {
            *(float4*)&crow[n0 + tx * TN] = *(float4*)&acc[i][0];
            if (TN == 8) *(float4*)&crow[n0 + tx * TN + 4] = *(float4*)&acc[i][4];
        }
    }
    __syncthreads();
    if (tid < TILE_N && (n0 + tid) < O) {
        double s = 0.0, q = 0.0;
#pragma unroll
        for (int w2 = 0; w2 < 8; w2++) {
            s += sPS[w2 * TILE_N + tid];
            q += sPQ[w2 * TILE_N + tid];
        }
        atomicAdd(&g_sum[n0 + tid],   s);
        atomicAdd(&g_sumsq[n0 + tid], q);
    }
}

// ---------------- plain tiled SGEMM for the final conv, KTILE=16 ---------------
__global__ __launch_bounds__(256, 2)
void gemm_tile(const float* __restrict__ A, int lda,
               const float* __restrict__ W, int ldw,
               const float* __restrict__ bias,
               float* __restrict__ Cmat, int ldc,
               int Kd, int Nc) {
    __shared__ __align__(16) float As[2][16][132];
    __shared__ __align__(16) float Bs[2][16][132];
    int tid = threadIdx.x;
    int tx = tid & 15, ty = tid >> 4;
    int m0 = blockIdx.x * 128, n0 = blockIdx.y * 128;
    int r  = tid >> 1, ks = (tid & 1) * 8;

    float acc[8][8];
#pragma unroll
    for (int i = 0; i < 8; i++)
#pragma unroll
        for (int j = 0; j < 8; j++) acc[i][j] = 0.f;

    const float* Arow = A + (size_t)(m0 + r) * lda;
    const float* Wrow = W + (size_t)(n0 + r) * ldw;

    int ntiles = (Kd + 15) / 16;
    float apf[8], wpf[8];
    load_h4(Arow, ks,     Kd, true, apf);
    load_h4(Arow, ks + 4, Kd, true, apf + 4);
    load_h4(Wrow, ks,     Kd, true, wpf);
    load_h4(Wrow, ks + 4, Kd, true, wpf + 4);
#pragma unroll
    for (int j = 0; j < 8; j++) { As[0][ks + j][r] = apf[j]; Bs[0][ks + j][r] = wpf[j]; }
    __syncthreads();

    for (int t = 0; t < ntiles; t++) {
        int p = t & 1;
        if (t + 1 < ntiles) {
            int k0 = (t + 1) * 16;
            load_h4(Arow, k0 + ks,     Kd, true, apf);
            load_h4(Arow, k0 + ks + 4, Kd, true, apf + 4);
            load_h4(Wrow, k0 + ks,     Kd, true, wpf);
            load_h4(Wrow, k0 + ks + 4, Kd, true, wpf + 4);
        }
#pragma unroll
        for (int k = 0; k < 16; k++) {
            float a[8], bb[8];
            *(float4*)(a)      = *(const float4*)&As[p][k][ty * 8];
            *(float4*)(a + 4)  = *(const float4*)&As[p][k][ty * 8 + 4];
            *(float4*)(bb)     = *(const float4*)&Bs[p][k][tx * 8];
            *(float4*)(bb + 4) = *(const float4*)&Bs[p][k][tx * 8 + 4];
#pragma unroll
            for (int i = 0; i < 8; i++)
#pragma unroll
                for (int j = 0; j < 8; j++)
                    acc[i][j] = fmaf(a[i], bb[j], acc[i][j]);
        }
        if (t + 1 < ntiles) {
#pragma unroll
            for (int j = 0; j < 8; j++) {
                As[1 - p][ks + j][r] = apf[j];
                Bs[1 - p][ks + j][r] = wpf[j];
            }
            __syncthreads();
        }
    }

#pragma unroll
    for (int i = 0; i < 8; i++) {
        float* crow = Cmat + (size_t)(m0 + ty * 8 + i) * ldc;
#pragma unroll
        for (int jj = 0; jj < 2; jj++) {
            int n = n0 + tx * 8 + jj * 4;
            float4 v;
            v.x = acc[i][jj * 4 + 0] + bias[n + 0];
            v.y = acc[i][jj * 4 + 1] + bias[n + 1];
            v.z = acc[i][jj * 4 + 2] + bias[n + 2];
            v.w = acc[i][jj * 4 + 3] + bias[n + 3];
            *(float4*)&crow[n] = v;
        }
    }
}

__global__ void finalize_stats(const float* __restrict__ gam,
                               const float* __restrict__ bet, int O, double cnt) {
    int o = blockIdx.x * blockDim.x + threadIdx.x;
    if (o >= O) return;
    double mean = g_sum[o] / cnt;
    double var  = g_sumsq[o] / cnt - mean * mean;
    float inv = rsqrtf((float)var + 1e-5f);
    float sc  = gam[o] * inv;
    g_scale[o] = sc;
    g_shift[o] = bet[o] - (float)mean * sc;
}

// ---------------- BN + LeakyReLU + max over k ---------------------------------
__global__ void bn_relu_max(int O, int outOff) {
    int t = blockIdx.x * blockDim.x + threadIdx.x;
    if (t >= BN_TOT * O) return;
    int o  = t % O;
    int bn = t / O;
    float sc = g_scale[o], sh = g_shift[o];
    float mx = neg_inf();
    size_t base = (size_t)bn * KNN * O + o;
#pragma unroll 5
    for (int k = 0; k < KNN; k++) {
        float v = g_hpre[base + (size_t)k * O];
        v = fmaf(v, sc, sh);
        v = (v >= 0.f) ? v : 0.2f * v;
        mx = fmaxf(mx, v);
    }
    g_xcat[(size_t)bn * LDCAT + outOff + o] = mx;
}

// ---------------- global max pool over N --------------------------------------
__global__ void max_over_n(float* __restrict__ out) {
    int t = blockIdx.x * blockDim.x + threadIdx.x;
    if (t >= BATCH * FIN_O) return;
    int o = t % FIN_O, b = t / FIN_O;
    const float* base = g_fin + (size_t)b * NPTS * FIN_O + o;
    float mx = neg_inf();
#pragma unroll 4
    for (int n = 0; n < NPTS; n++) mx = fmaxf(mx, base[(size_t)n * FIN_O]);
    out[t] = mx;
}

// ==============================================================================
extern "C" void kernel_launch(void* const* d_in, const int* in_sizes, int n_in,
                              void* d_out, int out_size) {
    const float* x = (const float*)d_in[0];
    const float* Wm[4], *bm[4], *gm[4], *bem[4];
    for (int i = 0; i < 4; i++) {
        Wm[i]  = (const float*)d_in[1 + 4 * i];
        bm[i]  = (const float*)d_in[2 + 4 * i];
        gm[i]  = (const float*)d_in[3 + 4 * i];
        bem[i] = (const float*)d_in[4 + 4 * i];
    }
    const float* Wf = (const float*)d_in[17];
    const float* bf = (const float*)d_in[18];
    float* out = (float*)d_out;

    float *hpre_ptr, *xcat_ptr, *fin_ptr;
    cudaGetSymbolAddress((void**)&hpre_ptr, g_hpre);
    cudaGetSymbolAddress((void**)&xcat_ptr, g_xcat);
    cudaGetSymbolAddress((void**)&fin_ptr,  g_fin);

    const int Hs[4]   = {64, 64, 128, 256};
    const int offs[4] = {0, 64, 128, 256};

    const float* hsrc = x;
    int ld = 3, C = 3;

    for (int i = 0; i < 4; i++) {
        int O = Hs[i];

        dist_gemm<<<dim3(NPTS / 128, NPTS / 128, BATCH), 256>>>(hsrc, ld, C);
        topk_kernel<<<BN_TOT / 8, 256>>>();
        zero_stats<<<1, 256>>>();

        if (i == 0) {
            edge1_kernel<<<M_EDGES / 64, 256>>>(hsrc, Wm[0], bm[0], hpre_ptr);
        } else if (O == 64) {
            edge_gemm<4><<<dim3(M_EDGES / 128, 1), 256>>>(
                hsrc, ld, C, Wm[i], bm[i], hpre_ptr, O);
        } else {
            edge_gemm<8><<<dim3(M_EDGES / 128, O / 128), 256>>>(
                hsrc, ld, C, Wm[i], bm[i], hpre_ptr, O);
        }

        finalize_stats<<<1, 256>>>(gm[i], bem[i], O, (double)M_EDGES);
        bn_relu_max<<<((size_t)BN_TOT * O + 255) / 256, 256>>>(O, offs[i]);

        hsrc = xcat_ptr + offs[i];
        ld = LDCAT;
        C  = O;
    }

    // final 1x1 conv (GEMM) + global max pool over N
    gemm_tile<<<dim3(BN_TOT / 128, FIN_O / 128), 256>>>(
        xcat_ptr, LDCAT, Wf, LDCAT, bf, fin_ptr, FIN_O, LDCAT, FIN_O);
    max_over_n<<<(BATCH * FIN_O + 255) / 256, 256>>>(out);
}

// round 16
// speedup vs baseline: 1.5955x; 1.0545x over previous
#include <cuda_runtime.h>
#include <cstdint>

#define BATCH 8
#define NPTS 2048
#define BN_TOT (BATCH * NPTS)          // 16384
#define KNN 20
#define M_EDGES (BN_TOT * KNN)         // 327680
#define LDCAT 512
#define FIN_O 1024
#define MAXBLK 2560

typedef unsigned long long ull;

// ---------------- scratch (device globals; no allocations allowed) -------------
__device__ float  g_dist[(size_t)BATCH * NPTS * NPTS];   // 134MB
__device__ int    g_idx [M_EDGES];
__device__ float  g_hpre[(size_t)M_EDGES * 256];         // pre-BN conv out, max O=256
__device__ float  g_xcat[(size_t)BN_TOT * LDCAT];
__device__ float  g_fin [(size_t)BN_TOT * FIN_O];
__device__ double g_partS[(size_t)MAXBLK * 256];         // per-block stat partials
__device__ double g_partQ[(size_t)MAXBLK * 256];
__device__ float  g_scale[256];
__device__ float  g_shift[256];

__device__ __forceinline__ float neg_inf() { return __int_as_float(0xff800000); }
__device__ __forceinline__ float pos_inf() { return __int_as_float(0x7f800000); }

// ---------------- packed fp32x2 helpers (each half = exact IEEE fp32 op) -------
__device__ __forceinline__ ull pack2(float x, float y) {
    ull r; asm("mov.b64 %0, {%1, %2};" : "=l"(r) : "f"(x), "f"(y)); return r;
}
__device__ __forceinline__ void fma2(ull& acc, ull a, ull b) {
    asm("fma.rn.f32x2 %0, %1, %2, %0;" : "+l"(acc) : "l"(a), "l"(b));
}
__device__ __forceinline__ ull sub2(ull a, ull b) {
    ull d; asm("sub.rn.f32x2 %0, %1, %2;" : "=l"(d) : "l"(a), "l"(b)); return d;
}
__device__ __forceinline__ float2 unpack2(ull v) {
    float2 f; asm("mov.b64 {%0, %1}, %2;" : "=f"(f.x), "=f"(f.y) : "l"(v)); return f;
}

// Vectorized loaders; values bitwise-identical to scalar forms.
__device__ __forceinline__ void load_h4(const float* __restrict__ row, int kk,
                                        int C, bool al, float v[4]) {
    if (al && kk + 3 < C) {
        float4 t = *(const float4*)&row[kk];
        v[0] = t.x; v[1] = t.y; v[2] = t.z; v[3] = t.w;
    } else {
#pragma unroll
        for (int j = 0; j < 4; j++) { int k = kk + j; v[j] = (k < C) ? row[k] : 0.f; }
    }
}

__device__ __forceinline__ void load_edge4(const float* __restrict__ rowN,
                                           const float* __restrict__ rowC,
                                           int kk, int C, int Kd, bool al, float v[4]) {
    if (al && kk + 3 < C) {
        float4 n = *(const float4*)&rowN[kk];
        float4 c = *(const float4*)&rowC[kk];
        v[0] = n.x - c.x; v[1] = n.y - c.y; v[2] = n.z - c.z; v[3] = n.w - c.w;
    } else if (al && kk >= C && kk + 3 < Kd) {
        float4 c = *(const float4*)&rowC[kk - C];
        v[0] = c.x; v[1] = c.y; v[2] = c.z; v[3] = c.w;
    } else {
#pragma unroll
        for (int j = 0; j < 4; j++) {
            int k = kk + j; float t = 0.f;
            if (k < C)       t = rowN[k] - rowC[k];
            else if (k < Kd) t = rowC[k - C];
            v[j] = t;
        }
    }
}

// ---------------- pairwise sq distances, DIFF FORM, symmetric, f32x2 -----------
// Each packed half runs the same sequential fmaf chain => bitwise == R15.
__global__ __launch_bounds__(256, 2)
void dist_gemm(const float* __restrict__ h, int ld, int C) {
    if (blockIdx.y > blockIdx.x) return;
    __shared__ __align__(16) float As[2][16][132];
    __shared__ __align__(16) float Bs[2][16][132];
    int b   = blockIdx.z;
    const float* hb = h + (size_t)b * NPTS * ld;
    int tid = threadIdx.x;
    int tx = tid & 15, ty = tid >> 4;
    int m0 = blockIdx.y * 128, n0 = blockIdx.x * 128;
    int r  = tid >> 1, ks = (tid & 1) * 8;
    bool al = ((ld & 3) == 0);

    ull acc2[8][4];
#pragma unroll
    for (int i = 0; i < 8; i++)
#pragma unroll
        for (int j = 0; j < 4; j++) acc2[i][j] = 0ull;

    const float* Arow = hb + (size_t)(m0 + r) * ld;
    const float* Brow = hb + (size_t)(n0 + r) * ld;

    int ntiles = (C + 15) / 16;
    float apf[8], bpf[8];
    load_h4(Arow, ks,     C, al, apf);
    load_h4(Arow, ks + 4, C, al, apf + 4);
    load_h4(Brow, ks,     C, al, bpf);
    load_h4(Brow, ks + 4, C, al, bpf + 4);
#pragma unroll
    for (int j = 0; j < 8; j++) { As[0][ks + j][r] = apf[j]; Bs[0][ks + j][r] = bpf[j]; }
    __syncthreads();

    for (int t = 0; t < ntiles; t++) {
        int p = t & 1;
        if (t + 1 < ntiles) {
            int k0 = (t + 1) * 16;
            load_h4(Arow, k0 + ks,     C, al, apf);
            load_h4(Arow, k0 + ks + 4, C, al, apf + 4);
            load_h4(Brow, k0 + ks,     C, al, bpf);
            load_h4(Brow, k0 + ks + 4, C, al, bpf + 4);
        }
#pragma unroll
        for (int k = 0; k < 16; k++) {
            float a[8];
            *(float4*)(a)     = *(const float4*)&As[p][k][ty * 8];
            *(float4*)(a + 4) = *(const float4*)&As[p][k][ty * 8 + 4];
            ull bp[4];
            const ull* bpp = (const ull*)&Bs[p][k][tx * 8];
#pragma unroll
            for (int j = 0; j < 4; j++) bp[j] = bpp[j];
#pragma unroll
            for (int i = 0; i < 8; i++) {
                ull ap = pack2(a[i], a[i]);
#pragma unroll
                for (int j = 0; j < 4; j++) {
                    ull d = sub2(ap, bp[j]);
                    fma2(acc2[i][j], d, d);
                }
            }
        }
        if (t + 1 < ntiles) {
#pragma unroll
            for (int j = 0; j < 8; j++) {
                As[1 - p][ks + j][r] = apf[j];
                Bs[1 - p][ks + j][r] = bpf[j];
            }
            __syncthreads();
        }
    }

    float acc[8][8];
#pragma unroll
    for (int i = 0; i < 8; i++)
#pragma unroll
        for (int j = 0; j < 4; j++) {
            float2 f = unpack2(acc2[i][j]);
            acc[i][2 * j] = f.x; acc[i][2 * j + 1] = f.y;
        }

    float* dbase = g_dist + (size_t)b * NPTS * NPTS;
#pragma unroll
    for (int i = 0; i < 8; i++) {
        float* drow = dbase + (size_t)(m0 + ty * 8 + i) * NPTS;
#pragma unroll
        for (int jj = 0; jj < 2; jj++) {
            float4 v;
            v.x = acc[i][jj * 4 + 0];
            v.y = acc[i][jj * 4 + 1];
            v.z = acc[i][jj * 4 + 2];
            v.w = acc[i][jj * 4 + 3];
            *(float4*)&drow[n0 + tx * 8 + jj * 4] = v;
        }
    }
    if (blockIdx.y != blockIdx.x) {
        __syncthreads();
        float (*Tst)[132] = (float(*)[132])&As[0][0][0];
        for (int c = 0; c < 4; c++) {
            if ((tx >> 2) == c) {
#pragma unroll
                for (int j = 0; j < 8; j++) {
                    int nl = (tx & 3) * 8 + j;
#pragma unroll
                    for (int i = 0; i < 8; i++)
                        Tst[nl][ty * 8 + i] = acc[i][j];
                }
            }
            __syncthreads();
            int nl2 = tid >> 3;
            int mc  = (tid & 7) * 16;
            float* dTrow = dbase + (size_t)(n0 + c * 32 + nl2) * NPTS + m0 + mc;
#pragma unroll
            for (int q = 0; q < 4; q++)
                *(float4*)&dTrow[q * 4] = *(const float4*)&Tst[nl2][mc + q * 4];
            __syncthreads();
        }
    }
}

// ---------------- warp-per-row top-K (UNCHANGED: bitwise-critical) -------------
__global__ void topk_kernel() {
    int gwarp = (blockIdx.x * blockDim.x + threadIdx.x) >> 5;
    int lane  = threadIdx.x & 31;
    if (gwarp >= BN_TOT) return;
    const float* drow = &g_dist[(size_t)gwarp * NPTS];

    float best[KNN];
    int   bidx[KNN];
#pragma unroll
    for (int i = 0; i < KNN; i++) { best[i] = pos_inf(); bidx[i] = -1; }

    for (int m = lane; m < NPTS; m += 32) {
        float d = drow[m];
        if (d < best[KNN - 1]) {
            int p = KNN - 1;
            while (p > 0 && best[p - 1] > d) {
                best[p] = best[p - 1]; bidx[p] = bidx[p - 1]; p--;
            }
            best[p] = d; bidx[p] = m;
        }
    }
    int ptr = 0;
    for (int s = 0; s < KNN; s++) {
        float v  = (ptr < KNN) ? best[ptr] : pos_inf();
        int   ci = (ptr < KNN) ? bidx[ptr] : -1;
        float mv = v; int ml = lane;
#pragma unroll
        for (int off = 16; off > 0; off >>= 1) {
            float ov = __shfl_down_sync(0xffffffffu, mv, off);
            int   ol = __shfl_down_sync(0xffffffffu, ml, off);
            if (ov < mv) { mv = ov; ml = ol; }
        }
        ml = __shfl_sync(0xffffffffu, ml, 0);
        int widx = __shfl_sync(0xffffffffu, ci, ml);
        if (lane == ml) ptr++;
        if (lane == 0) g_idx[gwarp * KNN + s] = widx;
    }
}

// ---------------- layer-1 specialized edge conv (C=3, Kd=6, O=64) --------------
// 512 blocks x 640 edges; register-carried stat partials -> scratch (no atomics).
#define E1_CHUNKS 10
__global__ __launch_bounds__(256, 4)
void edge1_kernel(const float* __restrict__ h,
                  const float* __restrict__ W,
                  const float* __restrict__ bias,
                  float* __restrict__ Cmat) {
    __shared__ float  sW[64][8];
    __shared__ float  sA[64][6];
    __shared__ float  sB[64];
    __shared__ double sPS[4][64];
    __shared__ double sPQ[4][64];
    int tid = threadIdx.x;
    if (tid < 64) sB[tid] = bias[tid];
    for (int i = tid; i < 64 * 6; i += 256) sW[i / 6][i % 6] = W[i];
    __syncthreads();

    int o  = tid & 63;
    int eg = tid >> 6;    // 0..3
    float w0 = sW[o][0], w1 = sW[o][1], w2 = sW[o][2];
    float w3 = sW[o][3], w4 = sW[o][4], w5 = sW[o][5];
    float bv = sB[o];
    double ps = 0.0, pq = 0.0;

    for (int c = 0; c < E1_CHUNKS; c++) {
        size_t base = (size_t)blockIdx.x * (64 * E1_CHUNKS) + c * 64;
        __syncthreads();
        if (tid < 64) {
            int m  = (int)base + tid;
            int bn = m / KNN;
            int b  = bn >> 11;
            int nbr = g_idx[m];
            const float* rc = h + (size_t)bn * 3;
            const float* rn = h + (size_t)((b << 11) + nbr) * 3;
            sA[tid][0] = rn[0] - rc[0];
            sA[tid][1] = rn[1] - rc[1];
            sA[tid][2] = rn[2] - rc[2];
            sA[tid][3] = rc[0];
            sA[tid][4] = rc[1];
            sA[tid][5] = rc[2];
        }
        __syncthreads();
#pragma unroll
        for (int e0 = 0; e0 < 64; e0 += 4) {
            int e = e0 + eg;
            float acc = 0.f;
            acc = fmaf(sA[e][0], w0, acc);
            acc = fmaf(sA[e][1], w1, acc);
            acc = fmaf(sA[e][2], w2, acc);
            acc = fmaf(sA[e][3], w3, acc);
            acc = fmaf(sA[e][4], w4, acc);
            acc = fmaf(sA[e][5], w5, acc);
            float v = acc + bv;
            Cmat[(base + e) * 64 + o] = v;
            ps += (double)v;
            pq += (double)v * (double)v;
        }
    }
    sPS[eg][o] = ps;
    sPQ[eg][o] = pq;
    __syncthreads();
    if (tid < 64) {
        double s = sPS[0][tid] + sPS[1][tid] + sPS[2][tid] + sPS[3][tid];
        double q = sPQ[0][tid] + sPQ[1][tid] + sPQ[2][tid] + sPQ[3][tid];
        g_partS[(size_t)blockIdx.x * 256 + tid] = s;
        g_partQ[(size_t)blockIdx.x * 256 + tid] = q;
    }
}

// ---------------- fused edge-feature GEMM + stats, f32x2, partial-array stats --
template<int TN>
__global__ __launch_bounds__(256, 2)
void edge_gemm(const float* __restrict__ h, int ld, int C,
               const float* __restrict__ W,
               const float* __restrict__ bias,
               float* __restrict__ Cmat, int O) {
    const int TILE_N = TN * 16;
    const int WN = (TN == 8) ? 8 : 4;
    const int Kd = 2 * C;
    __shared__ __align__(16) float As[2][16][132];
    __shared__ __align__(16) float Bs[2][16][TILE_N + 4];

    int tid = threadIdx.x;
    int tx = tid & 15, ty = tid >> 4;
    int m0 = blockIdx.x * 128, n0 = blockIdx.y * TILE_N;
    int r  = tid >> 1, ks = (tid & 1) * 8;
    bool al = ((ld & 3) == 0);

    ull accp[8][TN / 2];
#pragma unroll
    for (int i = 0; i < 8; i++)
#pragma unroll
        for (int j = 0; j < TN / 2; j++) accp[i][j] = 0ull;

    int m   = m0 + r;
    int bn  = m / KNN;
    int b   = bn >> 11;
    int nbr = g_idx[m];
    const float* rowC = h + (size_t)bn * ld;
    const float* rowN = h + (size_t)((b << 11) + nbr) * ld;

    int nw = (TN == 8) ? (tid >> 1) : (tid >> 2);
    int wk = (TN == 8) ? ((tid & 1) * 8) : ((tid & 3) * 4);
    bool wok = (n0 + nw) < O;
    const float* Wrow = W + (size_t)(n0 + nw) * Kd;

    int ntiles = (Kd + 15) / 16;
    float apf[8], wpf[8];
    load_edge4(rowN, rowC, ks,     C, Kd, al, apf);
    load_edge4(rowN, rowC, ks + 4, C, Kd, al, apf + 4);
    if (wok) {
        *(float4*)wpf = *(const float4*)&Wrow[wk];
        if (WN == 8) *(float4*)(wpf + 4) = *(const float4*)&Wrow[wk + 4];
    } else {
#pragma unroll
        for (int j = 0; j < WN; j++) wpf[j] = 0.f;
    }
#pragma unroll
    for (int j = 0; j < 8; j++) As[0][ks + j][r] = apf[j];
#pragma unroll
    for (int j = 0; j < WN; j++) Bs[0][wk + j][nw] = wpf[j];
    __syncthreads();

    for (int t = 0; t < ntiles; t++) {
        int p = t & 1;
        if (t + 1 < ntiles) {
            int k0 = (t + 1) * 16;
            load_edge4(rowN, rowC, k0 + ks,     C, Kd, al, apf);
            load_edge4(rowN, rowC, k0 + ks + 4, C, Kd, al, apf + 4);
            if (wok) {
                *(float4*)wpf = *(const float4*)&Wrow[k0 + wk];
                if (WN == 8) *(float4*)(wpf + 4) = *(const float4*)&Wrow[k0 + wk + 4];
            }
        }
#pragma unroll
        for (int k = 0; k < 16; k++) {
            float a[8];
            *(float4*)(a)     = *(const float4*)&As[p][k][ty * 8];
            *(float4*)(a + 4) = *(const float4*)&As[p][k][ty * 8 + 4];
            ull bp[TN / 2];
            const ull* bpp = (const ull*)&Bs[p][k][tx * TN];
#pragma unroll
            for (int j = 0; j < TN / 2; j++) bp[j] = bpp[j];
#pragma unroll
            for (int i = 0; i < 8; i++) {
                ull ap = pack2(a[i], a[i]);
#pragma unroll
                for (int j = 0; j < TN / 2; j++)
                    fma2(accp[i][j], ap, bp[j]);
            }
        }
        if (t + 1 < ntiles) {
#pragma unroll
            for (int j = 0; j < 8; j++) As[1 - p][ks + j][r] = apf[j];
#pragma unroll
            for (int j = 0; j < WN; j++) Bs[1 - p][wk + j][nw] = wpf[j];
            __syncthreads();
        }
    }

    float acc[8][TN];
#pragma unroll
    for (int i = 0; i < 8; i++)
#pragma unroll
        for (int j = 0; j < TN / 2; j++) {
            float2 f = unpack2(accp[i][j]);
            acc[i][2 * j] = f.x; acc[i][2 * j + 1] = f.y;
        }

    // ---- epilogue: bias, stats via shfl + staged smem -> partial arrays ----
    __syncthreads();
    double* sPS = (double*)&As[0][0][0];
    double* sPQ = (double*)&Bs[0][0][0];
    int w = tid >> 5, lane = tid & 31;
#pragma unroll
    for (int j = 0; j < TN; j++) {
        int col = tx * TN + j;
        float bv = ((n0 + col) < O) ? bias[n0 + col] : 0.f;
        double ps = 0.0, pq = 0.0;
#pragma unroll
        for (int i = 0; i < 8; i++) {
            float v = acc[i][j] + bv;
            acc[i][j] = v;
            ps += (double)v;
            pq += (double)v * (double)v;
        }
        ps += __shfl_xor_sync(0xffffffffu, ps, 16);
        pq += __shfl_xor_sync(0xffffffffu, pq, 16);
        if (lane < 16) { sPS[w * TILE_N + col] = ps; sPQ[w * TILE_N + col] = pq; }
    }
#pragma unroll
    for (int i = 0; i < 8; i++) {
        float* crow = Cmat + (size_t)(m0 + ty * 8 + i) * O;
        if (n0 + tx * TN + TN - 1 < O) {
            *(float4*)&crow[n0 + tx * TN] = *(float4*)&acc[i][0];
            if (TN == 8) *(float4*)&crow[n0 + tx * TN + 4] = *(float4*)&acc[i][4];
        }
    }
    __syncthreads();
    if (tid < TILE_N && (n0 + tid) < O) {
        double s = 0.0, q = 0.0;
#pragma unroll
        for (int w2 = 0; w2 < 8; w2++) {
            s += sPS[w2 * TILE_N + tid];
            q += sPQ[w2 * TILE_N + tid];
        }
        g_partS[(size_t)blockIdx.x * 256 + n0 + tid] = s;
        g_partQ[(size_t)blockIdx.x * 256 + n0 + tid] = q;
    }
}

// ---------------- plain tiled SGEMM for the final conv, f32x2 ------------------
__global__ __launch_bounds__(256, 2)
void gemm_tile(const float* __restrict__ A, int lda,
               const float* __restrict__ W, int ldw,
               const float* __restrict__ bias,
               float* __restrict__ Cmat, int ldc,
               int Kd, int Nc) {
    __shared__ __align__(16) float As[2][16][132];
    __shared__ __align__(16) float Bs[2][16][132];
    int tid = threadIdx.x;
    int tx = tid & 15, ty = tid >> 4;
    int m0 = blockIdx.x * 128, n0 = blockIdx.y * 128;
    int r  = tid >> 1, ks = (tid & 1) * 8;

    ull accp[8][4];
#pragma unroll
    for (int i = 0; i < 8; i++)
#pragma unroll
        for (int j = 0; j < 4; j++) accp[i][j] = 0ull;

    const float* Arow = A + (size_t)(m0 + r) * lda;
    const float* Wrow = W + (size_t)(n0 + r) * ldw;

    int ntiles = (Kd + 15) / 16;
    float apf[8], wpf[8];
    load_h4(Arow, ks,     Kd, true, apf);
    load_h4(Arow, ks + 4, Kd, true, apf + 4);
    load_h4(Wrow, ks,     Kd, true, wpf);
    load_h4(Wrow, ks + 4, Kd, true, wpf + 4);
#pragma unroll
    for (int j = 0; j < 8; j++) { As[0][ks + j][r] = apf[j]; Bs[0][ks + j][r] = wpf[j]; }
    __syncthreads();

    for (int t = 0; t < ntiles; t++) {
        int p = t & 1;
        if (t + 1 < ntiles) {
            int k0 = (t + 1) * 16;
            load_h4(Arow, k0 + ks,     Kd, true, apf);
            load_h4(Arow, k0 + ks + 4, Kd, true, apf + 4);
            load_h4(Wrow, k0 + ks,     Kd, true, wpf);
            load_h4(Wrow, k0 + ks + 4, Kd, true, wpf + 4);
        }
#pragma unroll
        for (int k = 0; k < 16; k++) {
            float a[8];
            *(float4*)(a)     = *(const float4*)&As[p][k][ty * 8];
            *(float4*)(a + 4) = *(const float4*)&As[p][k][ty * 8 + 4];
            ull bp[4];
            const ull* bpp = (const ull*)&Bs[p][k][tx * 8];
#pragma unroll
            for (int j = 0; j < 4; j++) bp[j] = bpp[j];
#pragma unroll
            for (int i = 0; i < 8; i++) {
                ull ap = pack2(a[i], a[i]);
#pragma unroll
                for (int j = 0; j < 4; j++)
                    fma2(accp[i][j], ap, bp[j]);
            }
        }
        if (t + 1 < ntiles) {
#pragma unroll
            for (int j = 0; j < 8; j++) {
                As[1 - p][ks + j][r] = apf[j];
                Bs[1 - p][ks + j][r] = wpf[j];
            }
            __syncthreads();
        }
    }

#pragma unroll
    for (int i = 0; i < 8; i++) {
        float acc[8];
#pragma unroll
        for (int j = 0; j < 4; j++) {
            float2 f = unpack2(accp[i][j]);
            acc[2 * j] = f.x; acc[2 * j + 1] = f.y;
        }
        float* crow = Cmat + (size_t)(m0 + ty * 8 + i) * ldc;
#pragma unroll
        for (int jj = 0; jj < 2; jj++) {
            int n = n0 + tx * 8 + jj * 4;
            float4 v;
            v.x = acc[jj * 4 + 0] + bias[n + 0];
            v.y = acc[jj * 4 + 1] + bias[n + 1];
            v.z = acc[jj * 4 + 2] + bias[n + 2];
            v.w = acc[jj * 4 + 3] + bias[n + 3];
            *(float4*)&crow[n] = v;
        }
    }
}

// ---------------- stats reduce: one block per output channel -------------------
__global__ void reduce_stats(const float* __restrict__ gam,
                             const float* __restrict__ bet,
                             int nblk, double cnt) {
    __shared__ double ss[256], sq[256];
    int o   = blockIdx.x;
    int tid = threadIdx.x;
    double s = 0.0, q = 0.0;
    for (int bidx = tid; bidx < nblk; bidx += 256) {
        s += g_partS[(size_t)bidx * 256 + o];
        q += g_partQ[(size_t)bidx * 256 + o];
    }
    ss[tid] = s; sq[tid] = q;
    __syncthreads();
    for (int st = 128; st > 0; st >>= 1) {
        if (tid < st) { ss[tid] += ss[tid + st]; sq[tid] += sq[tid + st]; }
        __syncthreads();
    }
    if (tid == 0) {
        double mean = ss[0] / cnt;
        double var  = sq[0] / cnt - mean * mean;
        float inv = rsqrtf((float)var + 1e-5f);
        float sc  = gam[o] * inv;
        g_scale[o] = sc;
        g_shift[o] = bet[o] - (float)mean * sc;
    }
}

// ---------------- BN + LeakyReLU + max over k ---------------------------------
__global__ void bn_relu_max(int O, int outOff) {
    int t = blockIdx.x * blockDim.x + threadIdx.x;
    if (t >= BN_TOT * O) return;
    int o  = t % O;
    int bn = t / O;
    float sc = g_scale[o], sh = g_shift[o];
    float mx = neg_inf();
    size_t base = (size_t)bn * KNN * O + o;
#pragma unroll 5
    for (int k = 0; k < KNN; k++) {
        float v = g_hpre[base + (size_t)k * O];
        v = fmaf(v, sc, sh);
        v = (v >= 0.f) ? v : 0.2f * v;
        mx = fmaxf(mx, v);
    }
    g_xcat[(size_t)bn * LDCAT + outOff + o] = mx;
}

// ---------------- global max pool over N --------------------------------------
__global__ void max_over_n(float* __restrict__ out) {
    int t = blockIdx.x * blockDim.x + threadIdx.x;
    if (t >= BATCH * FIN_O) return;
    int o = t % FIN_O, b = t / FIN_O;
    const float* base = g_fin + (size_t)b * NPTS * FIN_O + o;
    float mx = neg_inf();
#pragma unroll 4
    for (int n = 0; n < NPTS; n++) mx = fmaxf(mx, base[(size_t)n * FIN_O]);
    out[t] = mx;
}

// ==============================================================================
extern "C" void kernel_launch(void* const* d_in, const int* in_sizes, int n_in,
                              void* d_out, int out_size) {
    const float* x = (const float*)d_in[0];
    const float* Wm[4], *bm[4], *gm[4], *bem[4];
    for (int i = 0; i < 4; i++) {
        Wm[i]  = (const float*)d_in[1 + 4 * i];
        bm[i]  = (const float*)d_in[2 + 4 * i];
        gm[i]  = (const float*)d_in[3 + 4 * i];
        bem[i] = (const float*)d_in[4 + 4 * i];
    }
    const float* Wf = (const float*)d_in[17];
    const float* bf = (const float*)d_in[18];
    float* out = (float*)d_out;

    float *hpre_ptr, *xcat_ptr, *fin_ptr;
    cudaGetSymbolAddress((void**)&hpre_ptr, g_hpre);
    cudaGetSymbolAddress((void**)&xcat_ptr, g_xcat);
    cudaGetSymbolAddress((void**)&fin_ptr,  g_fin);

    const int Hs[4]   = {64, 64, 128, 256};
    const int offs[4] = {0, 64, 128, 256};

    const float* hsrc = x;
    int ld = 3, C = 3;

    for (int i = 0; i < 4; i++) {
        int O = Hs[i];

        dist_gemm<<<dim3(NPTS / 128, NPTS / 128, BATCH), 256>>>(hsrc, ld, C);
        topk_kernel<<<BN_TOT / 8, 256>>>();

        int nblk;
        if (i == 0) {
            nblk = M_EDGES / (64 * E1_CHUNKS);     // 512
            edge1_kernel<<<nblk, 256>>>(hsrc, Wm[0], bm[0], hpre_ptr);
        } else if (O == 64) {
            nblk = M_EDGES / 128;                  // 2560
            edge_gemm<4><<<dim3(nblk, 1), 256>>>(
                hsrc, ld, C, Wm[i], bm[i], hpre_ptr, O);
        } else {
            nblk = M_EDGES / 128;                  // 2560 (x-dim; y splits cols)
            edge_gemm<8><<<dim3(nblk, O / 128), 256>>>(
                hsrc, ld, C, Wm[i], bm[i], hpre_ptr, O);
        }

        reduce_stats<<<O, 256>>>(gm[i], bem[i], nblk, (double)M_EDGES);
        bn_relu_max<<<((size_t)BN_TOT * O + 255) / 256, 256>>>(O, offs[i]);

        hsrc = xcat_ptr + offs[i];
        ld = LDCAT;
        C  = O;
    }

    // final 1x1 conv (GEMM) + global max pool over N
    gemm_tile<<<dim3(BN_TOT / 128, FIN_O / 128), 256>>>(
        xcat_ptr, LDCAT, Wf, LDCAT, bf, fin_ptr, FIN_O, LDCAT, FIN_O);
    max_over_n<<<(BATCH * FIN_O + 255) / 256, 256>>>(out);
}